// round 7
// baseline (speedup 1.0000x reference)
#include <cuda_runtime.h>
#include <cstdint>

#define NN 50000
#define EE 800000
#define KDIM 128
#define DHID 128
#define DOUT 64
#define NB   ((NN + 255) / 256)   // 196 scan blocks

// ---------------- scratch (device globals; no allocs allowed) ----------------
__device__ int g_is64;             // 1 if edge_index is int64, 0 if int32
__device__ int g_deg[NN];
__device__ int g_rowstart[NN + 1];
__device__ int g_cursor[NN];
__device__ int g_esrc[EE];
__device__ int g_bsum[NB];
__device__ int g_boff[NB + 1];

__device__ float g_zl[NN * DHID];  // x @ W_l1  (gets aggregated)
__device__ float g_zr[NN * DHID];  // x @ W_r1  (self term)
__device__ float g_h [NN * DHID];  // layer-1 output
__device__ float g_ul[NN * DOUT];  // h @ W_l2  (gets aggregated)
__device__ float g_ur[NN * DOUT];  // h @ W_r2  (self term)

// ---------------- edge dtype detection ----------------
__global__ void detect_kernel(const int* __restrict__ ei32) {
    __shared__ int nz;
    if (threadIdx.x == 0) nz = 0;
    __syncthreads();
    for (int i = threadIdx.x; i < 1024; i += blockDim.x) {
        if (ei32[2 * i + 1] != 0) nz = 1;   // benign race
    }
    __syncthreads();
    if (threadIdx.x == 0) g_is64 = (nz == 0) ? 1 : 0;
}

__device__ __forceinline__ int load_src(const void* ei, int e) {
    return g_is64 ? (int)((const long long*)ei)[e] : ((const int*)ei)[e];
}
__device__ __forceinline__ int load_dst(const void* ei, int e) {
    return g_is64 ? (int)((const long long*)ei)[EE + e] : ((const int*)ei)[EE + e];
}

// ---------------- CSR build ----------------
__global__ void zero_deg_kernel() {
    int i = blockIdx.x * blockDim.x + threadIdx.x;
    if (i < NN) g_deg[i] = 0;
}

__global__ void hist_kernel(const void* __restrict__ ei) {
    int e = blockIdx.x * blockDim.x + threadIdx.x;
    if (e < EE) {
        int d = load_dst(ei, e);
        if ((unsigned)d < NN) atomicAdd(&g_deg[d], 1);
    }
}

__global__ void scanA_kernel() {
    __shared__ int sh[256];
    const int t = threadIdx.x;
    const int i = blockIdx.x * 256 + t;
    int v = (i < NN) ? g_deg[i] : 0;
    sh[t] = v;
    __syncthreads();
#pragma unroll
    for (int off = 1; off < 256; off <<= 1) {
        int u = (t >= off) ? sh[t - off] : 0;
        __syncthreads();
        sh[t] += u;
        __syncthreads();
    }
    if (i < NN) g_rowstart[i] = sh[t] - v;        // exclusive local prefix
    if (t == 255) g_bsum[blockIdx.x] = sh[255];   // block total
}

__global__ void scanB_kernel() {
    __shared__ int sh[256];
    const int t = threadIdx.x;
    int v = (t < NB) ? g_bsum[t] : 0;
    sh[t] = v;
    __syncthreads();
#pragma unroll
    for (int off = 1; off < 256; off <<= 1) {
        int u = (t >= off) ? sh[t - off] : 0;
        __syncthreads();
        sh[t] += u;
        __syncthreads();
    }
    if (t < NB) g_boff[t] = sh[t] - v;            // exclusive
    if (t == NB - 1) g_boff[NB] = sh[t];          // grand total
}

__global__ void scanC_kernel() {
    const int i = blockIdx.x * 256 + threadIdx.x;
    if (i < NN) {
        int r = g_rowstart[i] + g_boff[blockIdx.x];
        g_rowstart[i] = r;
        g_cursor[i]   = r;
    }
    if (i == 0) g_rowstart[NN] = g_boff[NB];
}

__global__ void fill_kernel(const void* __restrict__ ei) {
    int e = blockIdx.x * blockDim.x + threadIdx.x;
    if (e < EE) {
        int d = load_dst(ei, e);
        int s = load_src(ei, e);
        if ((unsigned)d < NN && (unsigned)s < NN) {
            int pos = atomicAdd(&g_cursor[d], 1);
            g_esrc[pos] = s;
        }
    }
}

// ---------------- tf32 tensor-core GEMM (3xTF32 split, ~fp32 precision) ----------------
// PTX: cvt with tf32 dst requires a .b32 register destination ("=r", not "=f").
__device__ __forceinline__ float tf32_hi(float v) {
    uint32_t r;
    asm("cvt.rna.tf32.f32 %0, %1;" : "=r"(r) : "f"(v));
    return __uint_as_float(r);
}

__device__ __forceinline__ void mma_tf32(float d[4], const uint32_t a[4], const uint32_t b[2]) {
    asm volatile(
        "mma.sync.aligned.m16n8k8.row.col.f32.tf32.tf32.f32 "
        "{%0,%1,%2,%3}, {%4,%5,%6,%7}, {%8,%9}, {%0,%1,%2,%3};\n"
        : "+f"(d[0]), "+f"(d[1]), "+f"(d[2]), "+f"(d[3])
        : "r"(a[0]), "r"(a[1]), "r"(a[2]), "r"(a[3]),
          "r"(b[0]), "r"(b[1]));
}

// C[M x BN] = A[M x 128] @ B[128 x BN].  BM=128, BK=16, 256 threads (8 warps, 2x4).
// Warp tile 64 x WN (WN=32 for BN=128, WN=16 for BN=64). m16n8k8 tf32 MMAs,
// hi/lo split applied at smem-store time; acc += lo*hi + hi*lo + hi*hi.
template <int BN, int WN>
__device__ __forceinline__
void gemm_tc_body(const float* __restrict__ A, const float* __restrict__ B,
                  float* __restrict__ C) {
    constexpr int BM = 128, BK = 16;
    constexpr int NT = WN / 8;         // n-tiles per warp
    __shared__ float As_hi[BM][BK + 1];
    __shared__ float As_lo[BM][BK + 1];
    __shared__ float Bs_hi[BK][BN + 1];
    __shared__ float Bs_lo[BK][BN + 1];

    const int tid = threadIdx.x;
    const int wid = tid >> 5, lane = tid & 31;
    const int gq = lane >> 2, tg = lane & 3;  // group-of-4 id, id-in-group
    const int warp_m = wid & 1;               // 0..1  (64 rows each)
    const int warp_n = wid >> 1;              // 0..3  (WN cols each)
    const int row0 = blockIdx.x * BM;

    float acc[4][NT][4];
#pragma unroll
    for (int mt = 0; mt < 4; mt++)
#pragma unroll
        for (int nt = 0; nt < NT; nt++)
#pragma unroll
            for (int r = 0; r < 4; r++) acc[mt][nt][r] = 0.0f;

    for (int k0 = 0; k0 < KDIM; k0 += BK) {
        // A tile: BM x BK = 2048 floats = 512 float4; 2 per thread
#pragma unroll
        for (int p = 0; p < 2; p++) {
            int idx = (p * 256 + tid) * 4;
            int m = idx / BK, k = idx % BK;
            float4 v = make_float4(0.f, 0.f, 0.f, 0.f);
            if (row0 + m < NN) v = *(const float4*)&A[(row0 + m) * KDIM + k0 + k];
            float h;
            h = tf32_hi(v.x); As_hi[m][k + 0] = h; As_lo[m][k + 0] = v.x - h;
            h = tf32_hi(v.y); As_hi[m][k + 1] = h; As_lo[m][k + 1] = v.y - h;
            h = tf32_hi(v.z); As_hi[m][k + 2] = h; As_lo[m][k + 2] = v.z - h;
            h = tf32_hi(v.w); As_hi[m][k + 3] = h; As_lo[m][k + 3] = v.w - h;
        }
        // B tile: BK x BN floats
#pragma unroll
        for (int p = 0; p < (BK * BN) / 1024; p++) {
            int idx = (p * 256 + tid) * 4;
            int k = idx / BN, n = idx % BN;
            float4 v = *(const float4*)&B[(k0 + k) * BN + n];
            float h;
            h = tf32_hi(v.x); Bs_hi[k][n + 0] = h; Bs_lo[k][n + 0] = v.x - h;
            h = tf32_hi(v.y); Bs_hi[k][n + 1] = h; Bs_lo[k][n + 1] = v.y - h;
            h = tf32_hi(v.z); Bs_hi[k][n + 2] = h; Bs_lo[k][n + 2] = v.z - h;
            h = tf32_hi(v.w); Bs_hi[k][n + 3] = h; Bs_lo[k][n + 3] = v.w - h;
        }
        __syncthreads();

#pragma unroll
        for (int ks = 0; ks < BK / 8; ks++) {
            const int kk = ks * 8;
            uint32_t ah[4][4], al[4][4];
#pragma unroll
            for (int mt = 0; mt < 4; mt++) {
                int r = warp_m * 64 + mt * 16 + gq;
                ah[mt][0] = __float_as_uint(As_hi[r    ][kk + tg]);
                ah[mt][1] = __float_as_uint(As_hi[r + 8][kk + tg]);
                ah[mt][2] = __float_as_uint(As_hi[r    ][kk + tg + 4]);
                ah[mt][3] = __float_as_uint(As_hi[r + 8][kk + tg + 4]);
                al[mt][0] = __float_as_uint(As_lo[r    ][kk + tg]);
                al[mt][1] = __float_as_uint(As_lo[r + 8][kk + tg]);
                al[mt][2] = __float_as_uint(As_lo[r    ][kk + tg + 4]);
                al[mt][3] = __float_as_uint(As_lo[r + 8][kk + tg + 4]);
            }
            uint32_t bh[NT][2], bl[NT][2];
#pragma unroll
            for (int nt = 0; nt < NT; nt++) {
                int c = warp_n * WN + nt * 8 + gq;
                bh[nt][0] = __float_as_uint(Bs_hi[kk + tg    ][c]);
                bh[nt][1] = __float_as_uint(Bs_hi[kk + tg + 4][c]);
                bl[nt][0] = __float_as_uint(Bs_lo[kk + tg    ][c]);
                bl[nt][1] = __float_as_uint(Bs_lo[kk + tg + 4][c]);
            }
#pragma unroll
            for (int mt = 0; mt < 4; mt++)
#pragma unroll
                for (int nt = 0; nt < NT; nt++) {
                    mma_tf32(acc[mt][nt], al[mt], bh[nt]);  // lo*hi
                    mma_tf32(acc[mt][nt], ah[mt], bl[nt]);  // hi*lo
                    mma_tf32(acc[mt][nt], ah[mt], bh[nt]);  // hi*hi
                }
        }
        __syncthreads();
    }

    // epilogue: c0/c1 at (row, 2*tg), c2/c3 at (row+8, 2*tg)
#pragma unroll
    for (int mt = 0; mt < 4; mt++) {
        int r = row0 + warp_m * 64 + mt * 16 + gq;
#pragma unroll
        for (int nt = 0; nt < NT; nt++) {
            int c = warp_n * WN + nt * 8 + 2 * tg;
            if (r < NN) {
                float2 v = make_float2(acc[mt][nt][0], acc[mt][nt][1]);
                *(float2*)&C[r * BN + c] = v;
            }
            if (r + 8 < NN) {
                float2 v = make_float2(acc[mt][nt][2], acc[mt][nt][3]);
                *(float2*)&C[(r + 8) * BN + c] = v;
            }
        }
    }
}

// Wrappers: scratch buffers bound on the DEVICE side only.
__global__ __launch_bounds__(256) void gemm_zl_kernel(const float* __restrict__ x,
                                                      const float* __restrict__ W) {
    gemm_tc_body<128, 32>(x, W, g_zl);
}
__global__ __launch_bounds__(256) void gemm_zr_kernel(const float* __restrict__ x,
                                                      const float* __restrict__ W) {
    gemm_tc_body<128, 32>(x, W, g_zr);
}
__global__ __launch_bounds__(256) void gemm_ul_kernel(const float* __restrict__ W) {
    gemm_tc_body<64, 16>(g_h, W, g_ul);
}
__global__ __launch_bounds__(256) void gemm_ur_kernel(const float* __restrict__ W) {
    gemm_tc_body<64, 16>(g_h, W, g_ur);
}

// ---------------- fused mean-aggregate + epilogue ----------------
// layer 1: h = relu(mean_agg(zl) + zr + b1), D=128, one warp per node, float4/lane
__global__ void agg_epi1_kernel(const float* __restrict__ b1) {
    int gw = (blockIdx.x * blockDim.x + threadIdx.x) >> 5;
    if (gw >= NN) return;
    int lane = threadIdx.x & 31;
    int c = lane * 4;
    int lo = g_rowstart[gw], hi = g_rowstart[gw + 1];

    float4 acc = make_float4(0.f, 0.f, 0.f, 0.f);
    int j = lo;
    for (; j + 4 <= hi; j += 4) {
        int s0 = g_esrc[j], s1 = g_esrc[j + 1], s2 = g_esrc[j + 2], s3 = g_esrc[j + 3];
        float4 v0 = *(const float4*)&g_zl[s0 * DHID + c];
        float4 v1 = *(const float4*)&g_zl[s1 * DHID + c];
        float4 v2 = *(const float4*)&g_zl[s2 * DHID + c];
        float4 v3 = *(const float4*)&g_zl[s3 * DHID + c];
        acc.x += (v0.x + v1.x) + (v2.x + v3.x);
        acc.y += (v0.y + v1.y) + (v2.y + v3.y);
        acc.z += (v0.z + v1.z) + (v2.z + v3.z);
        acc.w += (v0.w + v1.w) + (v2.w + v3.w);
    }
    for (; j < hi; j++) {
        int s = g_esrc[j];
        float4 v = *(const float4*)&g_zl[s * DHID + c];
        acc.x += v.x; acc.y += v.y; acc.z += v.z; acc.w += v.w;
    }
    float invd = 1.0f / (float)max(hi - lo, 1);
    float4 r  = *(const float4*)&g_zr[gw * DHID + c];
    float4 bb = *(const float4*)&b1[c];
    float4 o;
    o.x = fmaxf(fmaf(acc.x, invd, r.x + bb.x), 0.f);
    o.y = fmaxf(fmaf(acc.y, invd, r.y + bb.y), 0.f);
    o.z = fmaxf(fmaf(acc.z, invd, r.z + bb.z), 0.f);
    o.w = fmaxf(fmaf(acc.w, invd, r.w + bb.w), 0.f);
    *(float4*)&g_h[gw * DHID + c] = o;
}

// layer 2: out = mean_agg(ul) + ur + b2, D=64, one warp per node, float2/lane
__global__ void agg_epi2_kernel(const float* __restrict__ b2, float* __restrict__ out) {
    int gw = (blockIdx.x * blockDim.x + threadIdx.x) >> 5;
    if (gw >= NN) return;
    int lane = threadIdx.x & 31;
    int c = lane * 2;
    int lo = g_rowstart[gw], hi = g_rowstart[gw + 1];

    float2 acc = make_float2(0.f, 0.f);
    int j = lo;
    for (; j + 4 <= hi; j += 4) {
        int s0 = g_esrc[j], s1 = g_esrc[j + 1], s2 = g_esrc[j + 2], s3 = g_esrc[j + 3];
        float2 v0 = *(const float2*)&g_ul[s0 * DOUT + c];
        float2 v1 = *(const float2*)&g_ul[s1 * DOUT + c];
        float2 v2 = *(const float2*)&g_ul[s2 * DOUT + c];
        float2 v3 = *(const float2*)&g_ul[s3 * DOUT + c];
        acc.x += (v0.x + v1.x) + (v2.x + v3.x);
        acc.y += (v0.y + v1.y) + (v2.y + v3.y);
    }
    for (; j < hi; j++) {
        int s = g_esrc[j];
        float2 v = *(const float2*)&g_ul[s * DOUT + c];
        acc.x += v.x; acc.y += v.y;
    }
    float invd = 1.0f / (float)max(hi - lo, 1);
    float2 r  = *(const float2*)&g_ur[gw * DOUT + c];
    float2 bb = *(const float2*)&b2[c];
    float2 o;
    o.x = fmaf(acc.x, invd, r.x + bb.x);
    o.y = fmaf(acc.y, invd, r.y + bb.y);
    *(float2*)&out[gw * DOUT + c] = o;
}

// ---------------- launch ----------------
extern "C" void kernel_launch(void* const* d_in, const int* in_sizes, int n_in,
                              void* d_out, int out_size) {
    const float* x   = (const float*)d_in[0];
    const void*  ei  = d_in[1];                 // int32 OR int64 — detected on device
    const float* Wl1 = (const float*)d_in[2];
    const float* Wr1 = (const float*)d_in[3];
    const float* b1  = (const float*)d_in[4];
    const float* Wl2 = (const float*)d_in[5];
    const float* Wr2 = (const float*)d_in[6];
    const float* b2  = (const float*)d_in[7];
    float* out = (float*)d_out;

    // edge dtype detect + CSR build (shared by both layers)
    detect_kernel<<<1, 256>>>((const int*)ei);
    zero_deg_kernel<<<(NN + 255) / 256, 256>>>();
    hist_kernel<<<(EE + 255) / 256, 256>>>(ei);
    scanA_kernel<<<NB, 256>>>();
    scanB_kernel<<<1, 256>>>();
    scanC_kernel<<<NB, 256>>>();
    fill_kernel<<<(EE + 255) / 256, 256>>>(ei);

    const int gemm_grid = (NN + 127) / 128;  // 391

    // layer 1 projections (tf32 tensor cores, 3x split)
    gemm_zl_kernel<<<gemm_grid, 256>>>(x, Wl1);
    gemm_zr_kernel<<<gemm_grid, 256>>>(x, Wr1);
    // fused aggregate + bias + relu
    agg_epi1_kernel<<<(NN * 32 + 255) / 256, 256>>>(b1);

    // layer 2 projections
    gemm_ul_kernel<<<gemm_grid, 256>>>(Wl2);
    gemm_ur_kernel<<<gemm_grid, 256>>>(Wr2);
    // fused aggregate + bias -> output
    agg_epi2_kernel<<<(NN * 32 + 255) / 256, 256>>>(b2, out);
}

// round 9
// speedup vs baseline: 1.0674x; 1.0674x over previous
#include <cuda_runtime.h>
#include <cstdint>

#define NN 50000
#define EE 800000
#define KDIM 128
#define DHID 128
#define DOUT 64
#define NB   ((NN + 255) / 256)   // 196 scan blocks

// ---------------- scratch (device globals; no allocs allowed) ----------------
__device__ int g_is64;             // 1 if edge_index is int64, 0 if int32
__device__ int g_deg[NN];
__device__ int g_rowstart[NN + 1];
__device__ int g_cursor[NN];
__device__ int g_esrc[EE];
__device__ int g_bsum[NB];
__device__ int g_boff[NB + 1];

__device__ float g_zl[NN * DHID];  // x @ W_l1  (gets aggregated)
__device__ float g_zr[NN * DHID];  // x @ W_r1  (self term)
__device__ float g_h [NN * DHID];  // layer-1 output
__device__ float g_ul[NN * DOUT];  // h @ W_l2  (gets aggregated)
__device__ float g_ur[NN * DOUT];  // h @ W_r2  (self term)

// ---------------- edge dtype detection ----------------
__global__ void detect_kernel(const int* __restrict__ ei32) {
    __shared__ int nz;
    if (threadIdx.x == 0) nz = 0;
    __syncthreads();
    for (int i = threadIdx.x; i < 1024; i += blockDim.x) {
        if (ei32[2 * i + 1] != 0) nz = 1;   // benign race
    }
    __syncthreads();
    if (threadIdx.x == 0) g_is64 = (nz == 0) ? 1 : 0;
}

__device__ __forceinline__ int load_src(const void* ei, int e) {
    return g_is64 ? (int)((const long long*)ei)[e] : ((const int*)ei)[e];
}
__device__ __forceinline__ int load_dst(const void* ei, int e) {
    return g_is64 ? (int)((const long long*)ei)[EE + e] : ((const int*)ei)[EE + e];
}

// ---------------- CSR build ----------------
__global__ void zero_deg_kernel() {
    int i = blockIdx.x * blockDim.x + threadIdx.x;
    if (i < NN) g_deg[i] = 0;
}

__global__ void hist_kernel(const void* __restrict__ ei) {
    int e = blockIdx.x * blockDim.x + threadIdx.x;
    if (e < EE) {
        int d = load_dst(ei, e);
        if ((unsigned)d < NN) atomicAdd(&g_deg[d], 1);
    }
}

__global__ void scanA_kernel() {
    __shared__ int sh[256];
    const int t = threadIdx.x;
    const int i = blockIdx.x * 256 + t;
    int v = (i < NN) ? g_deg[i] : 0;
    sh[t] = v;
    __syncthreads();
#pragma unroll
    for (int off = 1; off < 256; off <<= 1) {
        int u = (t >= off) ? sh[t - off] : 0;
        __syncthreads();
        sh[t] += u;
        __syncthreads();
    }
    if (i < NN) g_rowstart[i] = sh[t] - v;        // exclusive local prefix
    if (t == 255) g_bsum[blockIdx.x] = sh[255];   // block total
}

__global__ void scanB_kernel() {
    __shared__ int sh[256];
    const int t = threadIdx.x;
    int v = (t < NB) ? g_bsum[t] : 0;
    sh[t] = v;
    __syncthreads();
#pragma unroll
    for (int off = 1; off < 256; off <<= 1) {
        int u = (t >= off) ? sh[t - off] : 0;
        __syncthreads();
        sh[t] += u;
        __syncthreads();
    }
    if (t < NB) g_boff[t] = sh[t] - v;            // exclusive
    if (t == NB - 1) g_boff[NB] = sh[t];          // grand total
}

__global__ void scanC_kernel() {
    const int i = blockIdx.x * 256 + threadIdx.x;
    if (i < NN) {
        int r = g_rowstart[i] + g_boff[blockIdx.x];
        g_rowstart[i] = r;
        g_cursor[i]   = r;
    }
    if (i == 0) g_rowstart[NN] = g_boff[NB];
}

__global__ void fill_kernel(const void* __restrict__ ei) {
    int e = blockIdx.x * blockDim.x + threadIdx.x;
    if (e < EE) {
        int d = load_dst(ei, e);
        int s = load_src(ei, e);
        if ((unsigned)d < NN && (unsigned)s < NN) {
            int pos = atomicAdd(&g_cursor[d], 1);
            g_esrc[pos] = s;
        }
    }
}

// ---------------- tf32 tensor-core fused dual-GEMM (3xTF32 split) ----------------
__device__ __forceinline__ float tf32_hi(float v) {
    uint32_t r;
    asm("cvt.rna.tf32.f32 %0, %1;" : "=r"(r) : "f"(v));
    return __uint_as_float(r);
}

__device__ __forceinline__ void mma_tf32(float d[4], const uint32_t a[4], const uint32_t b[2]) {
    asm volatile(
        "mma.sync.aligned.m16n8k8.row.col.f32.tf32.tf32.f32 "
        "{%0,%1,%2,%3}, {%4,%5,%6,%7}, {%8,%9}, {%0,%1,%2,%3};\n"
        : "+f"(d[0]), "+f"(d[1]), "+f"(d[2]), "+f"(d[3])
        : "r"(a[0]), "r"(a[1]), "r"(a[2]), "r"(a[3]),
          "r"(b[0]), "r"(b[1]));
}

// C1[M x HALF] = A @ B1, C2[M x HALF] = A @ B2, HALF = BN/2, K = 128.
// BM=128, 256 threads (8 warps as 2(m) x 4(n)), warp tile 64 x WN.
// Register double-buffering: prefetch tile t+1 from gmem during tile t's MMAs.
template <int BN, int BK, int WN>
__device__ __forceinline__
void gemm_fused_body(const float* __restrict__ A,
                     const float* __restrict__ B1, const float* __restrict__ B2,
                     float* __restrict__ C1, float* __restrict__ C2) {
    constexpr int BM = 128;
    constexpr int HALF = BN / 2;
    constexpr int NT = WN / 8;
    constexpr int NTILES = KDIM / BK;
    constexpr int AREG = (BM * BK) / 1024;   // float4 loads per thread for A
    constexpr int BREG = (BK * BN) / 1024;   // float4 loads per thread for B

    __shared__ float As_hi[BM][BK + 1];
    __shared__ float As_lo[BM][BK + 1];
    __shared__ float Bs_hi[BK][BN + 1];
    __shared__ float Bs_lo[BK][BN + 1];

    const int tid = threadIdx.x;
    const int wid = tid >> 5, lane = tid & 31;
    const int gq = lane >> 2, tg = lane & 3;  // group-of-4 id, id-in-group
    const int warp_m = wid & 1;               // 2 m-warps x 64 rows
    const int warp_n = wid >> 1;              // 4 n-warps x WN cols
    const int row0 = blockIdx.x * BM;

    float4 aprf[AREG], bprf[BREG];

    auto load_tile = [&](int t) {
#pragma unroll
        for (int p = 0; p < AREG; p++) {
            int idx = (p * 256 + tid) * 4;
            int m = idx / BK, k = idx % BK;
            float4 v = make_float4(0.f, 0.f, 0.f, 0.f);
            if (row0 + m < NN) v = *(const float4*)&A[(row0 + m) * KDIM + t * BK + k];
            aprf[p] = v;
        }
#pragma unroll
        for (int p = 0; p < BREG; p++) {
            int idx = (p * 256 + tid) * 4;
            int k = idx / BN, n = idx % BN;
            const float* src = (n < HALF) ? &B1[(t * BK + k) * HALF + n]
                                          : &B2[(t * BK + k) * HALF + (n - HALF)];
            bprf[p] = *(const float4*)src;
        }
    };
    auto store_tile = [&]() {
#pragma unroll
        for (int p = 0; p < AREG; p++) {
            int idx = (p * 256 + tid) * 4;
            int m = idx / BK, k = idx % BK;
            float h;
            h = tf32_hi(aprf[p].x); As_hi[m][k + 0] = h; As_lo[m][k + 0] = aprf[p].x - h;
            h = tf32_hi(aprf[p].y); As_hi[m][k + 1] = h; As_lo[m][k + 1] = aprf[p].y - h;
            h = tf32_hi(aprf[p].z); As_hi[m][k + 2] = h; As_lo[m][k + 2] = aprf[p].z - h;
            h = tf32_hi(aprf[p].w); As_hi[m][k + 3] = h; As_lo[m][k + 3] = aprf[p].w - h;
        }
#pragma unroll
        for (int p = 0; p < BREG; p++) {
            int idx = (p * 256 + tid) * 4;
            int k = idx / BN, n = idx % BN;
            float h;
            h = tf32_hi(bprf[p].x); Bs_hi[k][n + 0] = h; Bs_lo[k][n + 0] = bprf[p].x - h;
            h = tf32_hi(bprf[p].y); Bs_hi[k][n + 1] = h; Bs_lo[k][n + 1] = bprf[p].y - h;
            h = tf32_hi(bprf[p].z); Bs_hi[k][n + 2] = h; Bs_lo[k][n + 2] = bprf[p].z - h;
            h = tf32_hi(bprf[p].w); Bs_hi[k][n + 3] = h; Bs_lo[k][n + 3] = bprf[p].w - h;
        }
    };

    float acc[4][NT][4];
#pragma unroll
    for (int mt = 0; mt < 4; mt++)
#pragma unroll
        for (int nt = 0; nt < NT; nt++)
#pragma unroll
            for (int r = 0; r < 4; r++) acc[mt][nt][r] = 0.0f;

    load_tile(0);
    store_tile();
    __syncthreads();

    for (int t = 0; t < NTILES; t++) {
        if (t + 1 < NTILES) load_tile(t + 1);   // prefetch overlaps MMAs below

#pragma unroll
        for (int ks = 0; ks < BK / 8; ks++) {
            const int kk = ks * 8;
            uint32_t ah[4][4], al[4][4];
#pragma unroll
            for (int mt = 0; mt < 4; mt++) {
                int r = warp_m * 64 + mt * 16 + gq;
                ah[mt][0] = __float_as_uint(As_hi[r    ][kk + tg]);
                ah[mt][1] = __float_as_uint(As_hi[r + 8][kk + tg]);
                ah[mt][2] = __float_as_uint(As_hi[r    ][kk + tg + 4]);
                ah[mt][3] = __float_as_uint(As_hi[r + 8][kk + tg + 4]);
                al[mt][0] = __float_as_uint(As_lo[r    ][kk + tg]);
                al[mt][1] = __float_as_uint(As_lo[r + 8][kk + tg]);
                al[mt][2] = __float_as_uint(As_lo[r    ][kk + tg + 4]);
                al[mt][3] = __float_as_uint(As_lo[r + 8][kk + tg + 4]);
            }
#pragma unroll
            for (int nt = 0; nt < NT; nt++) {
                int c = warp_n * WN + nt * 8 + gq;
                uint32_t bh[2], bl[2];
                bh[0] = __float_as_uint(Bs_hi[kk + tg    ][c]);
                bh[1] = __float_as_uint(Bs_hi[kk + tg + 4][c]);
                bl[0] = __float_as_uint(Bs_lo[kk + tg    ][c]);
                bl[1] = __float_as_uint(Bs_lo[kk + tg + 4][c]);
#pragma unroll
                for (int mt = 0; mt < 4; mt++) {
                    mma_tf32(acc[mt][nt], al[mt], bh);  // lo*hi
                    mma_tf32(acc[mt][nt], ah[mt], bl);  // hi*lo
                    mma_tf32(acc[mt][nt], ah[mt], bh);  // hi*hi
                }
            }
        }
        __syncthreads();
        if (t + 1 < NTILES) {
            store_tile();
            __syncthreads();
        }
    }

    // epilogue: c0/c1 at (row, 2*tg), c2/c3 at (row+8, 2*tg); route halves to C1/C2
#pragma unroll
    for (int mt = 0; mt < 4; mt++) {
        int r = row0 + warp_m * 64 + mt * 16 + gq;
#pragma unroll
        for (int nt = 0; nt < NT; nt++) {
            int c = warp_n * WN + nt * 8 + 2 * tg;
            float* Cp = (c < HALF) ? C1 : C2;
            int cc = (c < HALF) ? c : c - HALF;
            if (r < NN) {
                float2 v = make_float2(acc[mt][nt][0], acc[mt][nt][1]);
                *(float2*)&Cp[r * HALF + cc] = v;
            }
            if (r + 8 < NN) {
                float2 v = make_float2(acc[mt][nt][2], acc[mt][nt][3]);
                *(float2*)&Cp[(r + 8) * HALF + cc] = v;
            }
        }
    }
}

// Wrappers: scratch buffers bound on the DEVICE side only.
__global__ __launch_bounds__(256) void gemm_f1_kernel(const float* __restrict__ x,
                                                      const float* __restrict__ Wl1,
                                                      const float* __restrict__ Wr1) {
    gemm_fused_body<256, 8, 64>(x, Wl1, Wr1, g_zl, g_zr);
}
__global__ __launch_bounds__(256) void gemm_f2_kernel(const float* __restrict__ Wl2,
                                                      const float* __restrict__ Wr2) {
    gemm_fused_body<128, 16, 32>(g_h, Wl2, Wr2, g_ul, g_ur);
}

// ---------------- fused mean-aggregate + epilogue ----------------
// layer 1: h = relu(mean_agg(zl) + zr + b1), D=128, one warp per node, float4/lane
__global__ void agg_epi1_kernel(const float* __restrict__ b1) {
    int gw = (blockIdx.x * blockDim.x + threadIdx.x) >> 5;
    if (gw >= NN) return;
    int lane = threadIdx.x & 31;
    int c = lane * 4;
    int lo = g_rowstart[gw], hi = g_rowstart[gw + 1];

    float4 acc = make_float4(0.f, 0.f, 0.f, 0.f);
    int j = lo;
    for (; j + 4 <= hi; j += 4) {
        int s0 = g_esrc[j], s1 = g_esrc[j + 1], s2 = g_esrc[j + 2], s3 = g_esrc[j + 3];
        float4 v0 = *(const float4*)&g_zl[s0 * DHID + c];
        float4 v1 = *(const float4*)&g_zl[s1 * DHID + c];
        float4 v2 = *(const float4*)&g_zl[s2 * DHID + c];
        float4 v3 = *(const float4*)&g_zl[s3 * DHID + c];
        acc.x += (v0.x + v1.x) + (v2.x + v3.x);
        acc.y += (v0.y + v1.y) + (v2.y + v3.y);
        acc.z += (v0.z + v1.z) + (v2.z + v3.z);
        acc.w += (v0.w + v1.w) + (v2.w + v3.w);
    }
    for (; j < hi; j++) {
        int s = g_esrc[j];
        float4 v = *(const float4*)&g_zl[s * DHID + c];
        acc.x += v.x; acc.y += v.y; acc.z += v.z; acc.w += v.w;
    }
    float invd = 1.0f / (float)max(hi - lo, 1);
    float4 r  = *(const float4*)&g_zr[gw * DHID + c];
    float4 bb = *(const float4*)&b1[c];
    float4 o;
    o.x = fmaxf(fmaf(acc.x, invd, r.x + bb.x), 0.f);
    o.y = fmaxf(fmaf(acc.y, invd, r.y + bb.y), 0.f);
    o.z = fmaxf(fmaf(acc.z, invd, r.z + bb.z), 0.f);
    o.w = fmaxf(fmaf(acc.w, invd, r.w + bb.w), 0.f);
    *(float4*)&g_h[gw * DHID + c] = o;
}

// layer 2: out = mean_agg(ul) + ur + b2, D=64, one warp per node, float2/lane
__global__ void agg_epi2_kernel(const float* __restrict__ b2, float* __restrict__ out) {
    int gw = (blockIdx.x * blockDim.x + threadIdx.x) >> 5;
    if (gw >= NN) return;
    int lane = threadIdx.x & 31;
    int c = lane * 2;
    int lo = g_rowstart[gw], hi = g_rowstart[gw + 1];

    float2 acc = make_float2(0.f, 0.f);
    int j = lo;
    for (; j + 4 <= hi; j += 4) {
        int s0 = g_esrc[j], s1 = g_esrc[j + 1], s2 = g_esrc[j + 2], s3 = g_esrc[j + 3];
        float2 v0 = *(const float2*)&g_ul[s0 * DOUT + c];
        float2 v1 = *(const float2*)&g_ul[s1 * DOUT + c];
        float2 v2 = *(const float2*)&g_ul[s2 * DOUT + c];
        float2 v3 = *(const float2*)&g_ul[s3 * DOUT + c];
        acc.x += (v0.x + v1.x) + (v2.x + v3.x);
        acc.y += (v0.y + v1.y) + (v2.y + v3.y);
    }
    for (; j < hi; j++) {
        int s = g_esrc[j];
        float2 v = *(const float2*)&g_ul[s * DOUT + c];
        acc.x += v.x; acc.y += v.y;
    }
    float invd = 1.0f / (float)max(hi - lo, 1);
    float2 r  = *(const float2*)&g_ur[gw * DOUT + c];
    float2 bb = *(const float2*)&b2[c];
    float2 o;
    o.x = fmaf(acc.x, invd, r.x + bb.x);
    o.y = fmaf(acc.y, invd, r.y + bb.y);
    *(float2*)&out[gw * DOUT + c] = o;
}

// ---------------- launch (single stream — stream fork removed after R8 infra fail) ----------------
extern "C" void kernel_launch(void* const* d_in, const int* in_sizes, int n_in,
                              void* d_out, int out_size) {
    const float* x   = (const float*)d_in[0];
    const void*  ei  = d_in[1];                 // int32 OR int64 — detected on device
    const float* Wl1 = (const float*)d_in[2];
    const float* Wr1 = (const float*)d_in[3];
    const float* b1  = (const float*)d_in[4];
    const float* Wl2 = (const float*)d_in[5];
    const float* Wr2 = (const float*)d_in[6];
    const float* b2  = (const float*)d_in[7];
    float* out = (float*)d_out;

    // CSR build (shared by both layers)
    detect_kernel<<<1, 256>>>((const int*)ei);
    zero_deg_kernel<<<(NN + 255) / 256, 256>>>();
    hist_kernel<<<(EE + 255) / 256, 256>>>(ei);
    scanA_kernel<<<NB, 256>>>();
    scanB_kernel<<<1, 256>>>();
    scanC_kernel<<<NB, 256>>>();
    fill_kernel<<<(EE + 255) / 256, 256>>>(ei);

    const int gemm_grid = (NN + 127) / 128;  // 391

    // layer-1 fused projections (tf32 tensor cores, 3x split)
    gemm_f1_kernel<<<gemm_grid, 256>>>(x, Wl1, Wr1);
    agg_epi1_kernel<<<(NN * 32 + 255) / 256, 256>>>(b1);

    // layer-2 fused projections + aggregation
    gemm_f2_kernel<<<gemm_grid, 256>>>(Wl2, Wr2);
    agg_epi2_kernel<<<(NN * 32 + 255) / 256, 256>>>(b2, out);
}

// round 11
// speedup vs baseline: 1.2926x; 1.2110x over previous
#include <cuda_runtime.h>
#include <cstdint>

#define NN 50000
#define EE 800000
#define KDIM 128
#define DHID 128
#define DOUT 64
#define NB   ((NN + 255) / 256)   // 196 scan blocks

// ---------------- scratch (device globals; no allocs allowed) ----------------
__device__ int g_is64;             // 1 if edge_index is int64, 0 if int32
__device__ int g_deg[NN];
__device__ int g_rowstart[NN + 1];
__device__ int g_cursor[NN];
__device__ int g_esrc[EE];
__device__ int g_bsum[NB];
__device__ int g_boff[NB + 1];

__device__ float g_zl[NN * DHID];  // x @ W_l1  (gets aggregated)
__device__ float g_zr[NN * DHID];  // x @ W_r1  (self term)
__device__ float g_h [NN * DHID];  // layer-1 output
__device__ float g_ul[NN * DOUT];  // h @ W_l2  (gets aggregated)
__device__ float g_ur[NN * DOUT];  // h @ W_r2  (self term)

// ---------------- edge dtype detection ----------------
__global__ void detect_kernel(const int* __restrict__ ei32) {
    __shared__ int nz;
    if (threadIdx.x == 0) nz = 0;
    __syncthreads();
    for (int i = threadIdx.x; i < 1024; i += blockDim.x) {
        if (ei32[2 * i + 1] != 0) nz = 1;   // benign race
    }
    __syncthreads();
    if (threadIdx.x == 0) g_is64 = (nz == 0) ? 1 : 0;
}

__device__ __forceinline__ int load_src(const void* ei, int e) {
    return g_is64 ? (int)((const long long*)ei)[e] : ((const int*)ei)[e];
}
__device__ __forceinline__ int load_dst(const void* ei, int e) {
    return g_is64 ? (int)((const long long*)ei)[EE + e] : ((const int*)ei)[EE + e];
}

// ---------------- CSR build ----------------
__global__ void zero_deg_kernel() {
    int i = blockIdx.x * blockDim.x + threadIdx.x;
    if (i < NN) g_deg[i] = 0;
}

__global__ void hist_kernel(const void* __restrict__ ei) {
    int e = blockIdx.x * blockDim.x + threadIdx.x;
    if (e < EE) {
        int d = load_dst(ei, e);
        if ((unsigned)d < NN) atomicAdd(&g_deg[d], 1);
    }
}

__global__ void scanA_kernel() {
    __shared__ int sh[256];
    const int t = threadIdx.x;
    const int i = blockIdx.x * 256 + t;
    int v = (i < NN) ? g_deg[i] : 0;
    sh[t] = v;
    __syncthreads();
#pragma unroll
    for (int off = 1; off < 256; off <<= 1) {
        int u = (t >= off) ? sh[t - off] : 0;
        __syncthreads();
        sh[t] += u;
        __syncthreads();
    }
    if (i < NN) g_rowstart[i] = sh[t] - v;        // exclusive local prefix
    if (t == 255) g_bsum[blockIdx.x] = sh[255];   // block total
}

__global__ void scanB_kernel() {
    __shared__ int sh[256];
    const int t = threadIdx.x;
    int v = (t < NB) ? g_bsum[t] : 0;
    sh[t] = v;
    __syncthreads();
#pragma unroll
    for (int off = 1; off < 256; off <<= 1) {
        int u = (t >= off) ? sh[t - off] : 0;
        __syncthreads();
        sh[t] += u;
        __syncthreads();
    }
    if (t < NB) g_boff[t] = sh[t] - v;            // exclusive
    if (t == NB - 1) g_boff[NB] = sh[t];          // grand total
}

__global__ void scanC_kernel() {
    const int i = blockIdx.x * 256 + threadIdx.x;
    if (i < NN) {
        int r = g_rowstart[i] + g_boff[blockIdx.x];
        g_rowstart[i] = r;
        g_cursor[i]   = r;
    }
    if (i == 0) g_rowstart[NN] = g_boff[NB];
}

__global__ void fill_kernel(const void* __restrict__ ei) {
    int e = blockIdx.x * blockDim.x + threadIdx.x;
    if (e < EE) {
        int d = load_dst(ei, e);
        int s = load_src(ei, e);
        if ((unsigned)d < NN && (unsigned)s < NN) {
            int pos = atomicAdd(&g_cursor[d], 1);
            g_esrc[pos] = s;
        }
    }
}

// ---------------- tf32 tensor-core fused dual-GEMM (3xTF32 split) ----------------
__device__ __forceinline__ float tf32_hi(float v) {
    uint32_t r;
    asm("cvt.rna.tf32.f32 %0, %1;" : "=r"(r) : "f"(v));
    return __uint_as_float(r);
}

__device__ __forceinline__ void mma_tf32(float d[4], const uint32_t a[4], const uint32_t b[2]) {
    asm volatile(
        "mma.sync.aligned.m16n8k8.row.col.f32.tf32.tf32.f32 "
        "{%0,%1,%2,%3}, {%4,%5,%6,%7}, {%8,%9}, {%0,%1,%2,%3};\n"
        : "+f"(d[0]), "+f"(d[1]), "+f"(d[2]), "+f"(d[3])
        : "r"(a[0]), "r"(a[1]), "r"(a[2]), "r"(a[3]),
          "r"(b[0]), "r"(b[1]));
}

// C1[M x HALF] = A @ B1, C2[M x HALF] = A @ B2, HALF = BN/2, K = 128.
// 512 threads = 16 warps as 4(m) x 4(n); BM=128 -> warp tile 32 x WN (WN=BN/4).
// acc = 2 x (WN/8) x 4 regs/thread (64 for BN=256) -> no spill.
// fp32 smem single-copy; hi/lo split at fragment-load time (cvt+sub).
// Register prefetch of k-tile t+1 overlaps tile t's MMAs.
// NOTE: smem row pads must keep row strides a multiple of 4 floats (16B) —
// float4 stores into As/Bs require it (the R10 "+1" pad faulted).
template <int BN, int BK>
__device__ __forceinline__
void gemm_fused_body(const float* __restrict__ A,
                     const float* __restrict__ B1, const float* __restrict__ B2,
                     float* __restrict__ C1, float* __restrict__ C2) {
    constexpr int BM = 128;
    constexpr int THREADS = 512;
    constexpr int HALF = BN / 2;
    constexpr int WN = BN / 4;
    constexpr int NT = WN / 8;
    constexpr int NTILES = KDIM / BK;
    constexpr int AREG = (BM * BK) / (THREADS * 4);
    constexpr int BREG = (BK * BN) / (THREADS * 4);

    __shared__ float As[BM][BK + 4];   // stride 20 floats = 80B, 16B-aligned rows
    __shared__ float Bs[BK][BN + 4];   // stride (BN+4) floats, 16B-aligned rows

    const int tid = threadIdx.x;
    const int wid = tid >> 5, lane = tid & 31;
    const int gq = lane >> 2, tg = lane & 3;   // group-of-4 id, id-in-group
    const int warp_m = wid & 3;                // 4 m-warps x 32 rows
    const int warp_n = wid >> 2;               // 4 n-warps x WN cols
    const int row0 = blockIdx.x * BM;

    float4 aprf[AREG], bprf[BREG];

    auto load_tile = [&](int t) {
#pragma unroll
        for (int p = 0; p < AREG; p++) {
            int idx = (p * THREADS + tid) * 4;
            int m = idx / BK, k = idx % BK;
            float4 v = make_float4(0.f, 0.f, 0.f, 0.f);
            if (row0 + m < NN) v = *(const float4*)&A[(row0 + m) * KDIM + t * BK + k];
            aprf[p] = v;
        }
#pragma unroll
        for (int p = 0; p < BREG; p++) {
            int idx = (p * THREADS + tid) * 4;
            int k = idx / BN, n = idx % BN;
            const float* src = (n < HALF) ? &B1[(t * BK + k) * HALF + n]
                                          : &B2[(t * BK + k) * HALF + (n - HALF)];
            bprf[p] = *(const float4*)src;
        }
    };
    auto store_tile = [&]() {
#pragma unroll
        for (int p = 0; p < AREG; p++) {
            int idx = (p * THREADS + tid) * 4;
            int m = idx / BK, k = idx % BK;
            *(float4*)&As[m][k] = aprf[p];
        }
#pragma unroll
        for (int p = 0; p < BREG; p++) {
            int idx = (p * THREADS + tid) * 4;
            int k = idx / BN, n = idx % BN;
            *(float4*)&Bs[k][n] = bprf[p];
        }
    };

    float acc[2][NT][4];
#pragma unroll
    for (int mt = 0; mt < 2; mt++)
#pragma unroll
        for (int nt = 0; nt < NT; nt++)
#pragma unroll
            for (int r = 0; r < 4; r++) acc[mt][nt][r] = 0.0f;

    load_tile(0);
    store_tile();
    __syncthreads();

    for (int t = 0; t < NTILES; t++) {
        if (t + 1 < NTILES) load_tile(t + 1);   // prefetch overlaps MMAs below

#pragma unroll
        for (int ks = 0; ks < BK / 8; ks++) {
            const int kk = ks * 8;
            uint32_t ah[2][4], al[2][4];
#pragma unroll
            for (int mt = 0; mt < 2; mt++) {
                int r = warp_m * 32 + mt * 16 + gq;
                float f0 = As[r    ][kk + tg];
                float f1 = As[r + 8][kk + tg];
                float f2 = As[r    ][kk + tg + 4];
                float f3 = As[r + 8][kk + tg + 4];
                float h0 = tf32_hi(f0), h1 = tf32_hi(f1), h2 = tf32_hi(f2), h3 = tf32_hi(f3);
                ah[mt][0] = __float_as_uint(h0); al[mt][0] = __float_as_uint(f0 - h0);
                ah[mt][1] = __float_as_uint(h1); al[mt][1] = __float_as_uint(f1 - h1);
                ah[mt][2] = __float_as_uint(h2); al[mt][2] = __float_as_uint(f2 - h2);
                ah[mt][3] = __float_as_uint(h3); al[mt][3] = __float_as_uint(f3 - h3);
            }
#pragma unroll
            for (int nt = 0; nt < NT; nt++) {
                int c = warp_n * WN + nt * 8 + gq;
                float g0 = Bs[kk + tg    ][c];
                float g1 = Bs[kk + tg + 4][c];
                float h0 = tf32_hi(g0), h1 = tf32_hi(g1);
                uint32_t bh[2], bl[2];
                bh[0] = __float_as_uint(h0); bl[0] = __float_as_uint(g0 - h0);
                bh[1] = __float_as_uint(h1); bl[1] = __float_as_uint(g1 - h1);
#pragma unroll
                for (int mt = 0; mt < 2; mt++) {
                    mma_tf32(acc[mt][nt], al[mt], bh);  // lo*hi
                    mma_tf32(acc[mt][nt], ah[mt], bl);  // hi*lo
                    mma_tf32(acc[mt][nt], ah[mt], bh);  // hi*hi
                }
            }
        }
        __syncthreads();
        if (t + 1 < NTILES) {
            store_tile();
            __syncthreads();
        }
    }

    // epilogue: c0/c1 at (row, 2*tg), c2/c3 at (row+8, 2*tg); route halves to C1/C2
#pragma unroll
    for (int mt = 0; mt < 2; mt++) {
        int r = row0 + warp_m * 32 + mt * 16 + gq;
#pragma unroll
        for (int nt = 0; nt < NT; nt++) {
            int c = warp_n * WN + nt * 8 + 2 * tg;
            float* Cp = (c < HALF) ? C1 : C2;
            int cc = (c < HALF) ? c : c - HALF;
            if (r < NN) {
                float2 v = make_float2(acc[mt][nt][0], acc[mt][nt][1]);
                *(float2*)&Cp[r * HALF + cc] = v;
            }
            if (r + 8 < NN) {
                float2 v = make_float2(acc[mt][nt][2], acc[mt][nt][3]);
                *(float2*)&Cp[(r + 8) * HALF + cc] = v;
            }
        }
    }
}

// Wrappers: scratch buffers bound on the DEVICE side only.
__global__ __launch_bounds__(512) void gemm_f1_kernel(const float* __restrict__ x,
                                                      const float* __restrict__ Wl1,
                                                      const float* __restrict__ Wr1) {
    gemm_fused_body<256, 16>(x, Wl1, Wr1, g_zl, g_zr);
}
__global__ __launch_bounds__(512) void gemm_f2_kernel(const float* __restrict__ Wl2,
                                                      const float* __restrict__ Wr2) {
    gemm_fused_body<128, 16>(g_h, Wl2, Wr2, g_ul, g_ur);
}

// ---------------- fused mean-aggregate + epilogue ----------------
// layer 1: h = relu(mean_agg(zl) + zr + b1), D=128, one warp per node, float4/lane
__global__ void agg_epi1_kernel(const float* __restrict__ b1) {
    int gw = (blockIdx.x * blockDim.x + threadIdx.x) >> 5;
    if (gw >= NN) return;
    int lane = threadIdx.x & 31;
    int c = lane * 4;
    int lo = g_rowstart[gw], hi = g_rowstart[gw + 1];

    float4 acc = make_float4(0.f, 0.f, 0.f, 0.f);
    int j = lo;
    for (; j + 4 <= hi; j += 4) {
        int s0 = g_esrc[j], s1 = g_esrc[j + 1], s2 = g_esrc[j + 2], s3 = g_esrc[j + 3];
        float4 v0 = *(const float4*)&g_zl[s0 * DHID + c];
        float4 v1 = *(const float4*)&g_zl[s1 * DHID + c];
        float4 v2 = *(const float4*)&g_zl[s2 * DHID + c];
        float4 v3 = *(const float4*)&g_zl[s3 * DHID + c];
        acc.x += (v0.x + v1.x) + (v2.x + v3.x);
        acc.y += (v0.y + v1.y) + (v2.y + v3.y);
        acc.z += (v0.z + v1.z) + (v2.z + v3.z);
        acc.w += (v0.w + v1.w) + (v2.w + v3.w);
    }
    for (; j < hi; j++) {
        int s = g_esrc[j];
        float4 v = *(const float4*)&g_zl[s * DHID + c];
        acc.x += v.x; acc.y += v.y; acc.z += v.z; acc.w += v.w;
    }
    float invd = 1.0f / (float)max(hi - lo, 1);
    float4 r  = *(const float4*)&g_zr[gw * DHID + c];
    float4 bb = *(const float4*)&b1[c];
    float4 o;
    o.x = fmaxf(fmaf(acc.x, invd, r.x + bb.x), 0.f);
    o.y = fmaxf(fmaf(acc.y, invd, r.y + bb.y), 0.f);
    o.z = fmaxf(fmaf(acc.z, invd, r.z + bb.z), 0.f);
    o.w = fmaxf(fmaf(acc.w, invd, r.w + bb.w), 0.f);
    *(float4*)&g_h[gw * DHID + c] = o;
}

// layer 2: out = mean_agg(ul) + ur + b2, D=64, one warp per node, float2/lane
__global__ void agg_epi2_kernel(const float* __restrict__ b2, float* __restrict__ out) {
    int gw = (blockIdx.x * blockDim.x + threadIdx.x) >> 5;
    if (gw >= NN) return;
    int lane = threadIdx.x & 31;
    int c = lane * 2;
    int lo = g_rowstart[gw], hi = g_rowstart[gw + 1];

    float2 acc = make_float2(0.f, 0.f);
    int j = lo;
    for (; j + 4 <= hi; j += 4) {
        int s0 = g_esrc[j], s1 = g_esrc[j + 1], s2 = g_esrc[j + 2], s3 = g_esrc[j + 3];
        float2 v0 = *(const float2*)&g_ul[s0 * DOUT + c];
        float2 v1 = *(const float2*)&g_ul[s1 * DOUT + c];
        float2 v2 = *(const float2*)&g_ul[s2 * DOUT + c];
        float2 v3 = *(const float2*)&g_ul[s3 * DOUT + c];
        acc.x += (v0.x + v1.x) + (v2.x + v3.x);
        acc.y += (v0.y + v1.y) + (v2.y + v3.y);
    }
    for (; j < hi; j++) {
        int s = g_esrc[j];
        float2 v = *(const float2*)&g_ul[s * DOUT + c];
        acc.x += v.x; acc.y += v.y;
    }
    float invd = 1.0f / (float)max(hi - lo, 1);
    float2 r  = *(const float2*)&g_ur[gw * DOUT + c];
    float2 bb = *(const float2*)&b2[c];
    float2 o;
    o.x = fmaf(acc.x, invd, r.x + bb.x);
    o.y = fmaf(acc.y, invd, r.y + bb.y);
    *(float2*)&out[gw * DOUT + c] = o;
}

// ---------------- launch (single stream) ----------------
extern "C" void kernel_launch(void* const* d_in, const int* in_sizes, int n_in,
                              void* d_out, int out_size) {
    const float* x   = (const float*)d_in[0];
    const void*  ei  = d_in[1];                 // int32 OR int64 — detected on device
    const float* Wl1 = (const float*)d_in[2];
    const float* Wr1 = (const float*)d_in[3];
    const float* b1  = (const float*)d_in[4];
    const float* Wl2 = (const float*)d_in[5];
    const float* Wr2 = (const float*)d_in[6];
    const float* b2  = (const float*)d_in[7];
    float* out = (float*)d_out;

    // CSR build (shared by both layers)
    detect_kernel<<<1, 256>>>((const int*)ei);
    zero_deg_kernel<<<(NN + 255) / 256, 256>>>();
    hist_kernel<<<(EE + 255) / 256, 256>>>(ei);
    scanA_kernel<<<NB, 256>>>();
    scanB_kernel<<<1, 256>>>();
    scanC_kernel<<<NB, 256>>>();
    fill_kernel<<<(EE + 255) / 256, 256>>>(ei);

    const int gemm_grid = (NN + 127) / 128;  // 391

    // layer-1 fused projections (tf32 tensor cores, 3x split)
    gemm_f1_kernel<<<gemm_grid, 512>>>(x, Wl1, Wr1);
    agg_epi1_kernel<<<(NN * 32 + 255) / 256, 256>>>(b1);

    // layer-2 fused projections + aggregation
    gemm_f2_kernel<<<gemm_grid, 512>>>(Wl2, Wr2);
    agg_epi2_kernel<<<(NN * 32 + 255) / 256, 256>>>(b2, out);
}

// round 12
// speedup vs baseline: 1.2945x; 1.0014x over previous
#include <cuda_runtime.h>
#include <cstdint>

#define NN 50000
#define EE 800000
#define KDIM 128
#define DHID 128
#define DOUT 64
#define NB   ((NN + 255) / 256)   // 196 scan blocks

// ---------------- scratch (device globals; no allocs allowed) ----------------
__device__ int g_is64;             // 1 if edge_index is int64, 0 if int32
__device__ int g_deg[NN];
__device__ int g_rowstart[NN + 1];
__device__ int g_cursor[NN];
__device__ int g_esrc[EE];
__device__ int g_bsum[NB];
__device__ int g_boff[NB + 1];

__device__ float g_zl[NN * DHID];  // x @ W_l1  (gets aggregated)
__device__ float g_zr[NN * DHID];  // x @ W_r1  (self term)
__device__ float g_h [NN * DHID];  // layer-1 output
__device__ float g_ul[NN * DOUT];  // h @ W_l2  (gets aggregated)
__device__ float g_ur[NN * DOUT];  // h @ W_r2  (self term)

// ---------------- edge dtype detection ----------------
__global__ void detect_kernel(const int* __restrict__ ei32) {
    __shared__ int nz;
    if (threadIdx.x == 0) nz = 0;
    __syncthreads();
    for (int i = threadIdx.x; i < 1024; i += blockDim.x) {
        if (ei32[2 * i + 1] != 0) nz = 1;   // benign race
    }
    __syncthreads();
    if (threadIdx.x == 0) g_is64 = (nz == 0) ? 1 : 0;
}

__device__ __forceinline__ int load_src(const void* ei, int e) {
    return g_is64 ? (int)((const long long*)ei)[e] : ((const int*)ei)[e];
}
__device__ __forceinline__ int load_dst(const void* ei, int e) {
    return g_is64 ? (int)((const long long*)ei)[EE + e] : ((const int*)ei)[EE + e];
}

// ---------------- CSR build ----------------
__global__ void zero_deg_kernel() {
    int i = blockIdx.x * blockDim.x + threadIdx.x;
    if (i < NN) g_deg[i] = 0;
}

__global__ void hist_kernel(const void* __restrict__ ei) {
    int e = blockIdx.x * blockDim.x + threadIdx.x;
    if (e < EE) {
        int d = load_dst(ei, e);
        if ((unsigned)d < NN) atomicAdd(&g_deg[d], 1);
    }
}

__global__ void scanA_kernel() {
    __shared__ int sh[256];
    const int t = threadIdx.x;
    const int i = blockIdx.x * 256 + t;
    int v = (i < NN) ? g_deg[i] : 0;
    sh[t] = v;
    __syncthreads();
#pragma unroll
    for (int off = 1; off < 256; off <<= 1) {
        int u = (t >= off) ? sh[t - off] : 0;
        __syncthreads();
        sh[t] += u;
        __syncthreads();
    }
    if (i < NN) g_rowstart[i] = sh[t] - v;        // exclusive local prefix
    if (t == 255) g_bsum[blockIdx.x] = sh[255];   // block total
}

__global__ void scanB_kernel() {
    __shared__ int sh[256];
    const int t = threadIdx.x;
    int v = (t < NB) ? g_bsum[t] : 0;
    sh[t] = v;
    __syncthreads();
#pragma unroll
    for (int off = 1; off < 256; off <<= 1) {
        int u = (t >= off) ? sh[t - off] : 0;
        __syncthreads();
        sh[t] += u;
        __syncthreads();
    }
    if (t < NB) g_boff[t] = sh[t] - v;            // exclusive
    if (t == NB - 1) g_boff[NB] = sh[t];          // grand total
}

__global__ void scanC_kernel() {
    const int i = blockIdx.x * 256 + threadIdx.x;
    if (i < NN) {
        int r = g_rowstart[i] + g_boff[blockIdx.x];
        g_rowstart[i] = r;
        g_cursor[i]   = r;
    }
    if (i == 0) g_rowstart[NN] = g_boff[NB];
}

__global__ void fill_kernel(const void* __restrict__ ei) {
    int e = blockIdx.x * blockDim.x + threadIdx.x;
    if (e < EE) {
        int d = load_dst(ei, e);
        int s = load_src(ei, e);
        if ((unsigned)d < NN && (unsigned)s < NN) {
            int pos = atomicAdd(&g_cursor[d], 1);
            g_esrc[pos] = s;
        }
    }
}

// ---------------- tf32 tensor-core fused dual-GEMM (3xTF32 split) ----------------
__device__ __forceinline__ float tf32_hi(float v) {
    uint32_t r;
    asm("cvt.rna.tf32.f32 %0, %1;" : "=r"(r) : "f"(v));
    return __uint_as_float(r);
}

__device__ __forceinline__ void mma_tf32(float d[4], const uint32_t a[4], const uint32_t b[2]) {
    asm volatile(
        "mma.sync.aligned.m16n8k8.row.col.f32.tf32.tf32.f32 "
        "{%0,%1,%2,%3}, {%4,%5,%6,%7}, {%8,%9}, {%0,%1,%2,%3};\n"
        : "+f"(d[0]), "+f"(d[1]), "+f"(d[2]), "+f"(d[3])
        : "r"(a[0]), "r"(a[1]), "r"(a[2]), "r"(a[3]),
          "r"(b[0]), "r"(b[1]));
}

// C1[M x HALF] = A @ B1, C2[M x HALF] = A @ B2, HALF = BN/2, K = 128.
// 512 threads = 16 warps as 4(m) x 4(n); BM=128 -> warp tile 32 x WN (WN=BN/4).
// acc = 2 x (WN/8) x 4 regs/thread (64 for BN=256) -> no spill.
// fp32 smem single-copy; hi/lo split at fragment-load time (cvt+sub).
// Register prefetch of k-tile t+1 overlaps tile t's MMAs.
// NOTE: smem row pads must keep row strides a multiple of 4 floats (16B) —
// float4 stores into As/Bs require it (the R10 "+1" pad faulted).
template <int BN, int BK>
__device__ __forceinline__
void gemm_fused_body(const float* __restrict__ A,
                     const float* __restrict__ B1, const float* __restrict__ B2,
                     float* __restrict__ C1, float* __restrict__ C2) {
    constexpr int BM = 128;
    constexpr int THREADS = 512;
    constexpr int HALF = BN / 2;
    constexpr int WN = BN / 4;
    constexpr int NT = WN / 8;
    constexpr int NTILES = KDIM / BK;
    constexpr int AREG = (BM * BK) / (THREADS * 4);
    constexpr int BREG = (BK * BN) / (THREADS * 4);

    __shared__ float As[BM][BK + 4];   // stride 20 floats = 80B, 16B-aligned rows
    __shared__ float Bs[BK][BN + 4];   // stride (BN+4) floats, 16B-aligned rows

    const int tid = threadIdx.x;
    const int wid = tid >> 5, lane = tid & 31;
    const int gq = lane >> 2, tg = lane & 3;   // group-of-4 id, id-in-group
    const int warp_m = wid & 3;                // 4 m-warps x 32 rows
    const int warp_n = wid >> 2;               // 4 n-warps x WN cols
    const int row0 = blockIdx.x * BM;

    float4 aprf[AREG], bprf[BREG];

    auto load_tile = [&](int t) {
#pragma unroll
        for (int p = 0; p < AREG; p++) {
            int idx = (p * THREADS + tid) * 4;
            int m = idx / BK, k = idx % BK;
            float4 v = make_float4(0.f, 0.f, 0.f, 0.f);
            if (row0 + m < NN) v = *(const float4*)&A[(row0 + m) * KDIM + t * BK + k];
            aprf[p] = v;
        }
#pragma unroll
        for (int p = 0; p < BREG; p++) {
            int idx = (p * THREADS + tid) * 4;
            int k = idx / BN, n = idx % BN;
            const float* src = (n < HALF) ? &B1[(t * BK + k) * HALF + n]
                                          : &B2[(t * BK + k) * HALF + (n - HALF)];
            bprf[p] = *(const float4*)src;
        }
    };
    auto store_tile = [&]() {
#pragma unroll
        for (int p = 0; p < AREG; p++) {
            int idx = (p * THREADS + tid) * 4;
            int m = idx / BK, k = idx % BK;
            *(float4*)&As[m][k] = aprf[p];
        }
#pragma unroll
        for (int p = 0; p < BREG; p++) {
            int idx = (p * THREADS + tid) * 4;
            int k = idx / BN, n = idx % BN;
            *(float4*)&Bs[k][n] = bprf[p];
        }
    };

    float acc[2][NT][4];
#pragma unroll
    for (int mt = 0; mt < 2; mt++)
#pragma unroll
        for (int nt = 0; nt < NT; nt++)
#pragma unroll
            for (int r = 0; r < 4; r++) acc[mt][nt][r] = 0.0f;

    load_tile(0);
    store_tile();
    __syncthreads();

    for (int t = 0; t < NTILES; t++) {
        if (t + 1 < NTILES) load_tile(t + 1);   // prefetch overlaps MMAs below

#pragma unroll
        for (int ks = 0; ks < BK / 8; ks++) {
            const int kk = ks * 8;
            uint32_t ah[2][4], al[2][4];
#pragma unroll
            for (int mt = 0; mt < 2; mt++) {
                int r = warp_m * 32 + mt * 16 + gq;
                float f0 = As[r    ][kk + tg];
                float f1 = As[r + 8][kk + tg];
                float f2 = As[r    ][kk + tg + 4];
                float f3 = As[r + 8][kk + tg + 4];
                float h0 = tf32_hi(f0), h1 = tf32_hi(f1), h2 = tf32_hi(f2), h3 = tf32_hi(f3);
                ah[mt][0] = __float_as_uint(h0); al[mt][0] = __float_as_uint(f0 - h0);
                ah[mt][1] = __float_as_uint(h1); al[mt][1] = __float_as_uint(f1 - h1);
                ah[mt][2] = __float_as_uint(h2); al[mt][2] = __float_as_uint(f2 - h2);
                ah[mt][3] = __float_as_uint(h3); al[mt][3] = __float_as_uint(f3 - h3);
            }
#pragma unroll
            for (int nt = 0; nt < NT; nt++) {
                int c = warp_n * WN + nt * 8 + gq;
                float g0 = Bs[kk + tg    ][c];
                float g1 = Bs[kk + tg + 4][c];
                float h0 = tf32_hi(g0), h1 = tf32_hi(g1);
                uint32_t bh[2], bl[2];
                bh[0] = __float_as_uint(h0); bl[0] = __float_as_uint(g0 - h0);
                bh[1] = __float_as_uint(h1); bl[1] = __float_as_uint(g1 - h1);
#pragma unroll
                for (int mt = 0; mt < 2; mt++) {
                    mma_tf32(acc[mt][nt], al[mt], bh);  // lo*hi
                    mma_tf32(acc[mt][nt], ah[mt], bl);  // hi*lo
                    mma_tf32(acc[mt][nt], ah[mt], bh);  // hi*hi
                }
            }
        }
        __syncthreads();
        if (t + 1 < NTILES) {
            store_tile();
            __syncthreads();
        }
    }

    // epilogue: c0/c1 at (row, 2*tg), c2/c3 at (row+8, 2*tg); route halves to C1/C2
#pragma unroll
    for (int mt = 0; mt < 2; mt++) {
        int r = row0 + warp_m * 32 + mt * 16 + gq;
#pragma unroll
        for (int nt = 0; nt < NT; nt++) {
            int c = warp_n * WN + nt * 8 + 2 * tg;
            float* Cp = (c < HALF) ? C1 : C2;
            int cc = (c < HALF) ? c : c - HALF;
            if (r < NN) {
                float2 v = make_float2(acc[mt][nt][0], acc[mt][nt][1]);
                *(float2*)&Cp[r * HALF + cc] = v;
            }
            if (r + 8 < NN) {
                float2 v = make_float2(acc[mt][nt][2], acc[mt][nt][3]);
                *(float2*)&Cp[(r + 8) * HALF + cc] = v;
            }
        }
    }
}

// Wrappers: scratch buffers bound on the DEVICE side only.
__global__ __launch_bounds__(512) void gemm_f1_kernel(const float* __restrict__ x,
                                                      const float* __restrict__ Wl1,
                                                      const float* __restrict__ Wr1) {
    gemm_fused_body<256, 16>(x, Wl1, Wr1, g_zl, g_zr);
}
__global__ __launch_bounds__(512) void gemm_f2_kernel(const float* __restrict__ Wl2,
                                                      const float* __restrict__ Wr2) {
    gemm_fused_body<128, 16>(g_h, Wl2, Wr2, g_ul, g_ur);
}

// ---------------- fused mean-aggregate + epilogue ----------------
// layer 1: h = relu(mean_agg(zl) + zr + b1), D=128, one warp per node, float4/lane
__global__ void agg_epi1_kernel(const float* __restrict__ b1) {
    int gw = (blockIdx.x * blockDim.x + threadIdx.x) >> 5;
    if (gw >= NN) return;
    int lane = threadIdx.x & 31;
    int c = lane * 4;
    int lo = g_rowstart[gw], hi = g_rowstart[gw + 1];

    float4 acc = make_float4(0.f, 0.f, 0.f, 0.f);
    int j = lo;
    for (; j + 4 <= hi; j += 4) {
        int s0 = g_esrc[j], s1 = g_esrc[j + 1], s2 = g_esrc[j + 2], s3 = g_esrc[j + 3];
        float4 v0 = *(const float4*)&g_zl[s0 * DHID + c];
        float4 v1 = *(const float4*)&g_zl[s1 * DHID + c];
        float4 v2 = *(const float4*)&g_zl[s2 * DHID + c];
        float4 v3 = *(const float4*)&g_zl[s3 * DHID + c];
        acc.x += (v0.x + v1.x) + (v2.x + v3.x);
        acc.y += (v0.y + v1.y) + (v2.y + v3.y);
        acc.z += (v0.z + v1.z) + (v2.z + v3.z);
        acc.w += (v0.w + v1.w) + (v2.w + v3.w);
    }
    for (; j < hi; j++) {
        int s = g_esrc[j];
        float4 v = *(const float4*)&g_zl[s * DHID + c];
        acc.x += v.x; acc.y += v.y; acc.z += v.z; acc.w += v.w;
    }
    float invd = 1.0f / (float)max(hi - lo, 1);
    float4 r  = *(const float4*)&g_zr[gw * DHID + c];
    float4 bb = *(const float4*)&b1[c];
    float4 o;
    o.x = fmaxf(fmaf(acc.x, invd, r.x + bb.x), 0.f);
    o.y = fmaxf(fmaf(acc.y, invd, r.y + bb.y), 0.f);
    o.z = fmaxf(fmaf(acc.z, invd, r.z + bb.z), 0.f);
    o.w = fmaxf(fmaf(acc.w, invd, r.w + bb.w), 0.f);
    *(float4*)&g_h[gw * DHID + c] = o;
}

// layer 2: out = mean_agg(ul) + ur + b2, D=64, one warp per node, float2/lane
__global__ void agg_epi2_kernel(const float* __restrict__ b2, float* __restrict__ out) {
    int gw = (blockIdx.x * blockDim.x + threadIdx.x) >> 5;
    if (gw >= NN) return;
    int lane = threadIdx.x & 31;
    int c = lane * 2;
    int lo = g_rowstart[gw], hi = g_rowstart[gw + 1];

    float2 acc = make_float2(0.f, 0.f);
    int j = lo;
    for (; j + 4 <= hi; j += 4) {
        int s0 = g_esrc[j], s1 = g_esrc[j + 1], s2 = g_esrc[j + 2], s3 = g_esrc[j + 3];
        float2 v0 = *(const float2*)&g_ul[s0 * DOUT + c];
        float2 v1 = *(const float2*)&g_ul[s1 * DOUT + c];
        float2 v2 = *(const float2*)&g_ul[s2 * DOUT + c];
        float2 v3 = *(const float2*)&g_ul[s3 * DOUT + c];
        acc.x += (v0.x + v1.x) + (v2.x + v3.x);
        acc.y += (v0.y + v1.y) + (v2.y + v3.y);
    }
    for (; j < hi; j++) {
        int s = g_esrc[j];
        float2 v = *(const float2*)&g_ul[s * DOUT + c];
        acc.x += v.x; acc.y += v.y;
    }
    float invd = 1.0f / (float)max(hi - lo, 1);
    float2 r  = *(const float2*)&g_ur[gw * DOUT + c];
    float2 bb = *(const float2*)&b2[c];
    float2 o;
    o.x = fmaf(acc.x, invd, r.x + bb.x);
    o.y = fmaf(acc.y, invd, r.y + bb.y);
    *(float2*)&out[gw * DOUT + c] = o;
}

// ---------------- launch (single stream) ----------------
extern "C" void kernel_launch(void* const* d_in, const int* in_sizes, int n_in,
                              void* d_out, int out_size) {
    const float* x   = (const float*)d_in[0];
    const void*  ei  = d_in[1];                 // int32 OR int64 — detected on device
    const float* Wl1 = (const float*)d_in[2];
    const float* Wr1 = (const float*)d_in[3];
    const float* b1  = (const float*)d_in[4];
    const float* Wl2 = (const float*)d_in[5];
    const float* Wr2 = (const float*)d_in[6];
    const float* b2  = (const float*)d_in[7];
    float* out = (float*)d_out;

    // CSR build (shared by both layers)
    detect_kernel<<<1, 256>>>((const int*)ei);
    zero_deg_kernel<<<(NN + 255) / 256, 256>>>();
    hist_kernel<<<(EE + 255) / 256, 256>>>(ei);
    scanA_kernel<<<NB, 256>>>();
    scanB_kernel<<<1, 256>>>();
    scanC_kernel<<<NB, 256>>>();
    fill_kernel<<<(EE + 255) / 256, 256>>>(ei);

    const int gemm_grid = (NN + 127) / 128;  // 391

    // layer-1 fused projections (tf32 tensor cores, 3x split)
    gemm_f1_kernel<<<gemm_grid, 512>>>(x, Wl1, Wr1);
    agg_epi1_kernel<<<(NN * 32 + 255) / 256, 256>>>(b1);

    // layer-2 fused projections + aggregation
    gemm_f2_kernel<<<gemm_grid, 512>>>(Wl2, Wr2);
    agg_epi2_kernel<<<(NN * 32 + 255) / 256, 256>>>(b2, out);
}

// round 13
// speedup vs baseline: 1.2959x; 1.0011x over previous
#include <cuda_runtime.h>
#include <cstdint>

#define NN 50000
#define EE 800000
#define KDIM 128
#define DHID 128
#define DOUT 64
#define NB   ((NN + 255) / 256)   // 196 scan blocks

// ---------------- scratch (device globals; no allocs allowed) ----------------
__device__ int g_is64;             // 1 if edge_index is int64, 0 if int32
__device__ int g_deg[NN];
__device__ int g_rowstart[NN + 1];
__device__ int g_cursor[NN];
__device__ int g_esrc[EE];
__device__ int g_bsum[NB];
__device__ int g_boff[NB + 1];

__device__ float g_zl[NN * DHID];  // x @ W_l1  (gets aggregated)
__device__ float g_zr[NN * DHID];  // x @ W_r1  (self term)
__device__ float g_h [NN * DHID];  // layer-1 output
__device__ float g_ul[NN * DOUT];  // h @ W_l2  (gets aggregated)
__device__ float g_ur[NN * DOUT];  // h @ W_r2  (self term)

// ---------------- init: zero degrees + edge dtype detection (fused) ----------------
__global__ void init_kernel(const int* __restrict__ ei32) {
    int i = blockIdx.x * blockDim.x + threadIdx.x;
    if (i < NN) g_deg[i] = 0;
    if (blockIdx.x == 0) {
        __shared__ int s_nz;
        if (threadIdx.x == 0) s_nz = 0;
        __syncthreads();
        bool nz = false;
        for (int j = threadIdx.x; j < 1024; j += blockDim.x)
            if (ei32[2 * j + 1] != 0) nz = true;
        if (__ballot_sync(0xffffffffu, nz) && (threadIdx.x & 31) == 0) atomicOr(&s_nz, 1);
        __syncthreads();
        if (threadIdx.x == 0) g_is64 = s_nz ? 0 : 1;
    }
}

__device__ __forceinline__ int load_src(const void* ei, int e) {
    return g_is64 ? (int)((const long long*)ei)[e] : ((const int*)ei)[e];
}
__device__ __forceinline__ int load_dst(const void* ei, int e) {
    return g_is64 ? (int)((const long long*)ei)[EE + e] : ((const int*)ei)[EE + e];
}

// ---------------- CSR build ----------------
__global__ void hist_kernel(const void* __restrict__ ei) {
    int e = blockIdx.x * blockDim.x + threadIdx.x;
    if (e < EE) {
        int d = load_dst(ei, e);
        if ((unsigned)d < NN) atomicAdd(&g_deg[d], 1);
    }
}

__global__ void scanA_kernel() {
    __shared__ int sh[256];
    const int t = threadIdx.x;
    const int i = blockIdx.x * 256 + t;
    int v = (i < NN) ? g_deg[i] : 0;
    sh[t] = v;
    __syncthreads();
#pragma unroll
    for (int off = 1; off < 256; off <<= 1) {
        int u = (t >= off) ? sh[t - off] : 0;
        __syncthreads();
        sh[t] += u;
        __syncthreads();
    }
    if (i < NN) g_rowstart[i] = sh[t] - v;        // exclusive local prefix
    if (t == 255) g_bsum[blockIdx.x] = sh[255];   // block total
}

__global__ void scanB_kernel() {
    __shared__ int sh[256];
    const int t = threadIdx.x;
    int v = (t < NB) ? g_bsum[t] : 0;
    sh[t] = v;
    __syncthreads();
#pragma unroll
    for (int off = 1; off < 256; off <<= 1) {
        int u = (t >= off) ? sh[t - off] : 0;
        __syncthreads();
        sh[t] += u;
        __syncthreads();
    }
    if (t < NB) g_boff[t] = sh[t] - v;            // exclusive
    if (t == NB - 1) g_boff[NB] = sh[t];          // grand total
}

__global__ void scanC_kernel() {
    const int i = blockIdx.x * 256 + threadIdx.x;
    if (i < NN) {
        int r = g_rowstart[i] + g_boff[blockIdx.x];
        g_rowstart[i] = r;
        g_cursor[i]   = r;
    }
    if (i == 0) g_rowstart[NN] = g_boff[NB];
}

__global__ void fill_kernel(const void* __restrict__ ei) {
    int e = blockIdx.x * blockDim.x + threadIdx.x;
    if (e < EE) {
        int d = load_dst(ei, e);
        int s = load_src(ei, e);
        if ((unsigned)d < NN && (unsigned)s < NN) {
            int pos = atomicAdd(&g_cursor[d], 1);
            g_esrc[pos] = s;
        }
    }
}

// ---------------- tf32 tensor-core fused dual-GEMM, full-K resident (3xTF32 split) ----------------
__device__ __forceinline__ float tf32_hi(float v) {
    uint32_t r;
    asm("cvt.rna.tf32.f32 %0, %1;" : "=r"(r) : "f"(v));
    return __uint_as_float(r);
}

__device__ __forceinline__ void mma_tf32(float d[4], const uint32_t a[4], const uint32_t b[2]) {
    asm volatile(
        "mma.sync.aligned.m16n8k8.row.col.f32.tf32.tf32.f32 "
        "{%0,%1,%2,%3}, {%4,%5,%6,%7}, {%8,%9}, {%0,%1,%2,%3};\n"
        : "+f"(d[0]), "+f"(d[1]), "+f"(d[2]), "+f"(d[3])
        : "r"(a[0]), "r"(a[1]), "r"(a[2]), "r"(a[3]),
          "r"(b[0]), "r"(b[1]));
}

// C1[M x HALF] = A @ B1, C2[M x HALF] = A @ B2, HALF = BN/2, K = 128 fully smem-resident.
// 512 threads = 16 warps as 4(m) x 4(n); BM=128 -> warp tile 32 x (BN/4).
// ONE smem fill + ONE sync, then all 16 k-steps of MMAs back-to-back.
// Row pads +8 floats: 16B-aligned rows AND conflict-free fragment loads
// (A: bank=4*gq+tg+... wait — stride 136 -> bank offset 8/row: 8*gq+tg distinct;
//  B: stride BN+8 -> 8*tg+gq distinct across all 32 lanes).
template <int BN>
__device__ __forceinline__
void gemm_fused_body(const float* __restrict__ A,
                     const float* __restrict__ B1, const float* __restrict__ B2,
                     float* __restrict__ C1, float* __restrict__ C2) {
    constexpr int BM = 128;
    constexpr int THREADS = 512;
    constexpr int HALF = BN / 2;
    constexpr int WN = BN / 4;
    constexpr int NT = WN / 8;
    constexpr int ASTR = KDIM + 8;   // 136
    constexpr int BSTR = BN + 8;

    extern __shared__ float smem[];
    float* As = smem;                 // [BM][ASTR]
    float* Bs = smem + BM * ASTR;     // [KDIM][BSTR]

    const int tid = threadIdx.x;
    const int wid = tid >> 5, lane = tid & 31;
    const int gq = lane >> 2, tg = lane & 3;   // group-of-4 id, id-in-group
    const int warp_m = wid & 3;                // 4 m-warps x 32 rows
    const int warp_n = wid >> 2;               // 4 n-warps x WN cols
    const int row0 = blockIdx.x * BM;

    // ---- fill A (BM x KDIM) ----
#pragma unroll
    for (int p = 0; p < (BM * KDIM) / (THREADS * 4); p++) {
        int idx = (p * THREADS + tid) * 4;
        int m = idx >> 7;            // /KDIM
        int k = idx & (KDIM - 1);
        float4 v = make_float4(0.f, 0.f, 0.f, 0.f);
        if (row0 + m < NN) v = *(const float4*)&A[(row0 + m) * KDIM + k];
        *(float4*)&As[m * ASTR + k] = v;
    }
    // ---- fill B (KDIM x BN), halves from B1|B2 ----
#pragma unroll
    for (int p = 0; p < (KDIM * BN) / (THREADS * 4); p++) {
        int idx = (p * THREADS + tid) * 4;
        int k = idx / BN;
        int n = idx % BN;
        const float* src = (n < HALF) ? &B1[k * HALF + n] : &B2[k * HALF + (n - HALF)];
        *(float4*)&Bs[k * BSTR + n] = *(const float4*)src;
    }
    __syncthreads();

    float acc[2][NT][4];
#pragma unroll
    for (int mt = 0; mt < 2; mt++)
#pragma unroll
        for (int nt = 0; nt < NT; nt++)
#pragma unroll
            for (int r = 0; r < 4; r++) acc[mt][nt][r] = 0.0f;

#pragma unroll 1
    for (int ks = 0; ks < KDIM / 8; ks++) {
        const int kk = ks * 8;
        uint32_t ah[2][4], al[2][4];
#pragma unroll
        for (int mt = 0; mt < 2; mt++) {
            int r = warp_m * 32 + mt * 16 + gq;
            float f0 = As[(r    ) * ASTR + kk + tg];
            float f1 = As[(r + 8) * ASTR + kk + tg];
            float f2 = As[(r    ) * ASTR + kk + tg + 4];
            float f3 = As[(r + 8) * ASTR + kk + tg + 4];
            float h0 = tf32_hi(f0), h1 = tf32_hi(f1), h2 = tf32_hi(f2), h3 = tf32_hi(f3);
            ah[mt][0] = __float_as_uint(h0); al[mt][0] = __float_as_uint(f0 - h0);
            ah[mt][1] = __float_as_uint(h1); al[mt][1] = __float_as_uint(f1 - h1);
            ah[mt][2] = __float_as_uint(h2); al[mt][2] = __float_as_uint(f2 - h2);
            ah[mt][3] = __float_as_uint(h3); al[mt][3] = __float_as_uint(f3 - h3);
        }
#pragma unroll
        for (int nt = 0; nt < NT; nt++) {
            int c = warp_n * WN + nt * 8 + gq;
            float g0 = Bs[(kk + tg    ) * BSTR + c];
            float g1 = Bs[(kk + tg + 4) * BSTR + c];
            float h0 = tf32_hi(g0), h1 = tf32_hi(g1);
            uint32_t bh[2], bl[2];
            bh[0] = __float_as_uint(h0); bl[0] = __float_as_uint(g0 - h0);
            bh[1] = __float_as_uint(h1); bl[1] = __float_as_uint(g1 - h1);
#pragma unroll
            for (int mt = 0; mt < 2; mt++) {
                mma_tf32(acc[mt][nt], al[mt], bh);  // lo*hi
                mma_tf32(acc[mt][nt], ah[mt], bl);  // hi*lo
                mma_tf32(acc[mt][nt], ah[mt], bh);  // hi*hi
            }
        }
    }

    // epilogue: c0/c1 at (row, 2*tg), c2/c3 at (row+8, 2*tg); route halves to C1/C2
#pragma unroll
    for (int mt = 0; mt < 2; mt++) {
        int r = row0 + warp_m * 32 + mt * 16 + gq;
#pragma unroll
        for (int nt = 0; nt < NT; nt++) {
            int c = warp_n * WN + nt * 8 + 2 * tg;
            float* Cp = (c < HALF) ? C1 : C2;
            int cc = (c < HALF) ? c : c - HALF;
            if (r < NN) {
                float2 v = make_float2(acc[mt][nt][0], acc[mt][nt][1]);
                *(float2*)&Cp[r * HALF + cc] = v;
            }
            if (r + 8 < NN) {
                float2 v = make_float2(acc[mt][nt][2], acc[mt][nt][3]);
                *(float2*)&Cp[(r + 8) * HALF + cc] = v;
            }
        }
    }
}

#define SMEM_F1 ((128 * (KDIM + 8) + KDIM * (256 + 8)) * 4)   // 204800 B
#define SMEM_F2 ((128 * (KDIM + 8) + KDIM * (128 + 8)) * 4)   // 139264 B

// Wrappers: scratch buffers bound on the DEVICE side only.
__global__ __launch_bounds__(512) void gemm_f1_kernel(const float* __restrict__ x,
                                                      const float* __restrict__ Wl1,
                                                      const float* __restrict__ Wr1) {
    gemm_fused_body<256>(x, Wl1, Wr1, g_zl, g_zr);
}
__global__ __launch_bounds__(512) void gemm_f2_kernel(const float* __restrict__ Wl2,
                                                      const float* __restrict__ Wr2) {
    gemm_fused_body<128>(g_h, Wl2, Wr2, g_ul, g_ur);
}

// ---------------- fused mean-aggregate + epilogue ----------------
// layer 1: h = relu(mean_agg(zl) + zr + b1), D=128, one warp per node, float4/lane
__global__ void agg_epi1_kernel(const float* __restrict__ b1) {
    int gw = (blockIdx.x * blockDim.x + threadIdx.x) >> 5;
    if (gw >= NN) return;
    int lane = threadIdx.x & 31;
    int c = lane * 4;
    int lo = g_rowstart[gw], hi = g_rowstart[gw + 1];

    float4 acc = make_float4(0.f, 0.f, 0.f, 0.f);
    int j = lo;
    for (; j + 4 <= hi; j += 4) {
        int s0 = g_esrc[j], s1 = g_esrc[j + 1], s2 = g_esrc[j + 2], s3 = g_esrc[j + 3];
        float4 v0 = *(const float4*)&g_zl[s0 * DHID + c];
        float4 v1 = *(const float4*)&g_zl[s1 * DHID + c];
        float4 v2 = *(const float4*)&g_zl[s2 * DHID + c];
        float4 v3 = *(const float4*)&g_zl[s3 * DHID + c];
        acc.x += (v0.x + v1.x) + (v2.x + v3.x);
        acc.y += (v0.y + v1.y) + (v2.y + v3.y);
        acc.z += (v0.z + v1.z) + (v2.z + v3.z);
        acc.w += (v0.w + v1.w) + (v2.w + v3.w);
    }
    for (; j < hi; j++) {
        int s = g_esrc[j];
        float4 v = *(const float4*)&g_zl[s * DHID + c];
        acc.x += v.x; acc.y += v.y; acc.z += v.z; acc.w += v.w;
    }
    float invd = 1.0f / (float)max(hi - lo, 1);
    float4 r  = *(const float4*)&g_zr[gw * DHID + c];
    float4 bb = *(const float4*)&b1[c];
    float4 o;
    o.x = fmaxf(fmaf(acc.x, invd, r.x + bb.x), 0.f);
    o.y = fmaxf(fmaf(acc.y, invd, r.y + bb.y), 0.f);
    o.z = fmaxf(fmaf(acc.z, invd, r.z + bb.z), 0.f);
    o.w = fmaxf(fmaf(acc.w, invd, r.w + bb.w), 0.f);
    *(float4*)&g_h[gw * DHID + c] = o;
}

// layer 2: out = mean_agg(ul) + ur + b2, D=64, one warp per node, float2/lane
__global__ void agg_epi2_kernel(const float* __restrict__ b2, float* __restrict__ out) {
    int gw = (blockIdx.x * blockDim.x + threadIdx.x) >> 5;
    if (gw >= NN) return;
    int lane = threadIdx.x & 31;
    int c = lane * 2;
    int lo = g_rowstart[gw], hi = g_rowstart[gw + 1];

    float2 acc = make_float2(0.f, 0.f);
    int j = lo;
    for (; j + 4 <= hi; j += 4) {
        int s0 = g_esrc[j], s1 = g_esrc[j + 1], s2 = g_esrc[j + 2], s3 = g_esrc[j + 3];
        float2 v0 = *(const float2*)&g_ul[s0 * DOUT + c];
        float2 v1 = *(const float2*)&g_ul[s1 * DOUT + c];
        float2 v2 = *(const float2*)&g_ul[s2 * DOUT + c];
        float2 v3 = *(const float2*)&g_ul[s3 * DOUT + c];
        acc.x += (v0.x + v1.x) + (v2.x + v3.x);
        acc.y += (v0.y + v1.y) + (v2.y + v3.y);
    }
    for (; j < hi; j++) {
        int s = g_esrc[j];
        float2 v = *(const float2*)&g_ul[s * DOUT + c];
        acc.x += v.x; acc.y += v.y;
    }
    float invd = 1.0f / (float)max(hi - lo, 1);
    float2 r  = *(const float2*)&g_ur[gw * DOUT + c];
    float2 bb = *(const float2*)&b2[c];
    float2 o;
    o.x = fmaf(acc.x, invd, r.x + bb.x);
    o.y = fmaf(acc.y, invd, r.y + bb.y);
    *(float2*)&out[gw * DOUT + c] = o;
}

// ---------------- launch (single stream) ----------------
extern "C" void kernel_launch(void* const* d_in, const int* in_sizes, int n_in,
                              void* d_out, int out_size) {
    const float* x   = (const float*)d_in[0];
    const void*  ei  = d_in[1];                 // int32 OR int64 — detected on device
    const float* Wl1 = (const float*)d_in[2];
    const float* Wr1 = (const float*)d_in[3];
    const float* b1  = (const float*)d_in[4];
    const float* Wl2 = (const float*)d_in[5];
    const float* Wr2 = (const float*)d_in[6];
    const float* b2  = (const float*)d_in[7];
    float* out = (float*)d_out;

    // Opt-in to >48KB dynamic smem (host-side attribute set; not a stream op,
    // not an allocation — capture-legal, idempotent).
    cudaFuncSetAttribute(gemm_f1_kernel, cudaFuncAttributeMaxDynamicSharedMemorySize, SMEM_F1);
    cudaFuncSetAttribute(gemm_f2_kernel, cudaFuncAttributeMaxDynamicSharedMemorySize, SMEM_F2);

    // CSR build (shared by both layers)
    init_kernel<<<(NN + 255) / 256, 256>>>((const int*)ei);
    hist_kernel<<<(EE + 255) / 256, 256>>>(ei);
    scanA_kernel<<<NB, 256>>>();
    scanB_kernel<<<1, 256>>>();
    scanC_kernel<<<NB, 256>>>();
    fill_kernel<<<(EE + 255) / 256, 256>>>(ei);

    const int gemm_grid = (NN + 127) / 128;  // 391

    // layer-1 fused projections (tf32 tensor cores, 3x split, full-K resident)
    gemm_f1_kernel<<<gemm_grid, 512, SMEM_F1>>>(x, Wl1, Wr1);
    agg_epi1_kernel<<<(NN * 32 + 255) / 256, 256>>>(b1);

    // layer-2 fused projections + aggregation
    gemm_f2_kernel<<<gemm_grid, 512, SMEM_F2>>>(Wl2, Wr2);
    agg_epi2_kernel<<<(NN * 32 + 255) / 256, 256>>>(b2, out);
}

// round 14
// speedup vs baseline: 1.3651x; 1.0534x over previous
#include <cuda_runtime.h>
#include <cstdint>

#define NN 50000
#define EE 800000
#define KDIM 128
#define DHID 128
#define DOUT 64
#define NB   ((NN + 255) / 256)   // 196 scan blocks

// ---------------- scratch (device globals; no allocs allowed) ----------------
// NOTE: g_deg relies on static zero-init for the FIRST call; every launch
// re-zeroes it at the tail of agg_epi2 (after its last read in scanA).
__device__ int g_deg[NN];
__device__ int g_rowstart[NN + 1];
__device__ int g_cursor[NN];
__device__ int g_esrc[EE];
__device__ int g_bsum[NB];

__device__ float g_zl[NN * DHID];  // x @ W_l1  (gets aggregated)
__device__ float g_zr[NN * DHID];  // x @ W_r1  (self term)
__device__ float g_h [NN * DHID];  // layer-1 output
__device__ float g_ul[NN * DOUT];  // h @ W_l2  (gets aggregated)
__device__ float g_ur[NN * DOUT];  // h @ W_r2  (self term)

// ---------------- per-block edge dtype detection (no global state) ----------------
// int64 little-endian with values in [0, NN): odd 32-bit words are all 0.
// Each block samples the first 2048 ints (1024 odd words) itself.
template <int THREADS, int PER>
__device__ __forceinline__ bool detect_is64(const int* __restrict__ ei32, int* s_nz) {
    if (threadIdx.x == 0) *s_nz = 0;
    __syncthreads();
    bool nz = false;
#pragma unroll
    for (int p = 0; p < PER; p++) {
        int i = threadIdx.x + p * THREADS;      // i in [0, 1024)
        nz |= (ei32[2 * i + 1] != 0);
    }
    if (__ballot_sync(0xffffffffu, nz) && (threadIdx.x & 31) == 0) *s_nz = 1;
    __syncthreads();
    return (*s_nz == 0);
}

__device__ __forceinline__ int edge_at(const void* ei, bool is64, long long idx) {
    return is64 ? (int)((const long long*)ei)[idx] : ((const int*)ei)[idx];
}

// ---------------- tf32 helpers ----------------
__device__ __forceinline__ float tf32_hi(float v) {
    uint32_t r;
    asm("cvt.rna.tf32.f32 %0, %1;" : "=r"(r) : "f"(v));
    return __uint_as_float(r);
}

__device__ __forceinline__ void mma_tf32(float d[4], const uint32_t a[4], const uint32_t b[2]) {
    asm volatile(
        "mma.sync.aligned.m16n8k8.row.col.f32.tf32.tf32.f32 "
        "{%0,%1,%2,%3}, {%4,%5,%6,%7}, {%8,%9}, {%0,%1,%2,%3};\n"
        : "+f"(d[0]), "+f"(d[1]), "+f"(d[2]), "+f"(d[3])
        : "r"(a[0]), "r"(a[1]), "r"(a[2]), "r"(a[3]),
          "r"(b[0]), "r"(b[1]));
}

// ---------------- tf32 fused dual-GEMM body, full-K resident (3xTF32 split) ----------------
// Identical math to R13; virtual block id passed in so it can live inside a
// role-split kernel.
template <int BN>
__device__ __forceinline__
void gemm_fused_body(int vbid, const float* __restrict__ A,
                     const float* __restrict__ B1, const float* __restrict__ B2,
                     float* __restrict__ C1, float* __restrict__ C2) {
    constexpr int BM = 128;
    constexpr int THREADS = 512;
    constexpr int HALF = BN / 2;
    constexpr int WN = BN / 4;
    constexpr int NT = WN / 8;
    constexpr int ASTR = KDIM + 8;   // 136 floats: 16B-aligned rows, conflict-free frags
    constexpr int BSTR = BN + 8;

    extern __shared__ float smem[];
    float* As = smem;                 // [BM][ASTR]
    float* Bs = smem + BM * ASTR;     // [KDIM][BSTR]

    const int tid = threadIdx.x;
    const int wid = tid >> 5, lane = tid & 31;
    const int gq = lane >> 2, tg = lane & 3;
    const int warp_m = wid & 3;
    const int warp_n = wid >> 2;
    const int row0 = vbid * BM;

#pragma unroll
    for (int p = 0; p < (BM * KDIM) / (THREADS * 4); p++) {
        int idx = (p * THREADS + tid) * 4;
        int m = idx >> 7;
        int k = idx & (KDIM - 1);
        float4 v = make_float4(0.f, 0.f, 0.f, 0.f);
        if (row0 + m < NN) v = *(const float4*)&A[(row0 + m) * KDIM + k];
        *(float4*)&As[m * ASTR + k] = v;
    }
#pragma unroll
    for (int p = 0; p < (KDIM * BN) / (THREADS * 4); p++) {
        int idx = (p * THREADS + tid) * 4;
        int k = idx / BN;
        int n = idx % BN;
        const float* src = (n < HALF) ? &B1[k * HALF + n] : &B2[k * HALF + (n - HALF)];
        *(float4*)&Bs[k * BSTR + n] = *(const float4*)src;
    }
    __syncthreads();

    float acc[2][NT][4];
#pragma unroll
    for (int mt = 0; mt < 2; mt++)
#pragma unroll
        for (int nt = 0; nt < NT; nt++)
#pragma unroll
            for (int r = 0; r < 4; r++) acc[mt][nt][r] = 0.0f;

#pragma unroll 1
    for (int ks = 0; ks < KDIM / 8; ks++) {
        const int kk = ks * 8;
        uint32_t ah[2][4], al[2][4];
#pragma unroll
        for (int mt = 0; mt < 2; mt++) {
            int r = warp_m * 32 + mt * 16 + gq;
            float f0 = As[(r    ) * ASTR + kk + tg];
            float f1 = As[(r + 8) * ASTR + kk + tg];
            float f2 = As[(r    ) * ASTR + kk + tg + 4];
            float f3 = As[(r + 8) * ASTR + kk + tg + 4];
            float h0 = tf32_hi(f0), h1 = tf32_hi(f1), h2 = tf32_hi(f2), h3 = tf32_hi(f3);
            ah[mt][0] = __float_as_uint(h0); al[mt][0] = __float_as_uint(f0 - h0);
            ah[mt][1] = __float_as_uint(h1); al[mt][1] = __float_as_uint(f1 - h1);
            ah[mt][2] = __float_as_uint(h2); al[mt][2] = __float_as_uint(f2 - h2);
            ah[mt][3] = __float_as_uint(h3); al[mt][3] = __float_as_uint(f3 - h3);
        }
#pragma unroll
        for (int nt = 0; nt < NT; nt++) {
            int c = warp_n * WN + nt * 8 + gq;
            float g0 = Bs[(kk + tg    ) * BSTR + c];
            float g1 = Bs[(kk + tg + 4) * BSTR + c];
            float h0 = tf32_hi(g0), h1 = tf32_hi(g1);
            uint32_t bh[2], bl[2];
            bh[0] = __float_as_uint(h0); bl[0] = __float_as_uint(g0 - h0);
            bh[1] = __float_as_uint(h1); bl[1] = __float_as_uint(g1 - h1);
#pragma unroll
            for (int mt = 0; mt < 2; mt++) {
                mma_tf32(acc[mt][nt], al[mt], bh);  // lo*hi
                mma_tf32(acc[mt][nt], ah[mt], bl);  // hi*lo
                mma_tf32(acc[mt][nt], ah[mt], bh);  // hi*hi
            }
        }
    }

#pragma unroll
    for (int mt = 0; mt < 2; mt++) {
        int r = row0 + warp_m * 32 + mt * 16 + gq;
#pragma unroll
        for (int nt = 0; nt < NT; nt++) {
            int c = warp_n * WN + nt * 8 + 2 * tg;
            float* Cp = (c < HALF) ? C1 : C2;
            int cc = (c < HALF) ? c : c - HALF;
            if (r < NN) {
                float2 v = make_float2(acc[mt][nt][0], acc[mt][nt][1]);
                *(float2*)&Cp[r * HALF + cc] = v;
            }
            if (r + 8 < NN) {
                float2 v = make_float2(acc[mt][nt][2], acc[mt][nt][3]);
                *(float2*)&Cp[(r + 8) * HALF + cc] = v;
            }
        }
    }
}

#define SMEM_F1 ((128 * (KDIM + 8) + KDIM * (256 + 8)) * 4)   // 204800 B
#define SMEM_F2 ((128 * (KDIM + 8) + KDIM * (128 + 8)) * 4)   // 139264 B

#define GEMM_GRID ((NN + 127) / 128)          // 391 gemm blocks
#define HIST_BLOCKS 128
#define K1_GRID (GEMM_GRID + HIST_BLOCKS)     // 519; every 4th block (bx%4==3, bx<512) is hist

// ---------------- K1: layer-1 fused GEMM + degree histogram (role-split) ----------------
__global__ __launch_bounds__(512) void gemm1_hist_kernel(const float* __restrict__ x,
                                                         const float* __restrict__ Wl1,
                                                         const float* __restrict__ Wr1,
                                                         const void* __restrict__ ei) {
    const int bx = blockIdx.x;
    const bool is_hist = (bx < 512) && ((bx & 3) == 3);
    if (is_hist) {
        __shared__ int s_nz;
        bool is64 = detect_is64<512, 2>((const int*)ei, &s_nz);
        const int hid = bx >> 2;                         // 0..127
        const int stride = HIST_BLOCKS * 512;
        for (int e = hid * 512 + threadIdx.x; e < EE; e += stride) {
            int d = edge_at(ei, is64, (long long)EE + e);
            if ((unsigned)d < NN) atomicAdd(&g_deg[d], 1);
        }
    } else {
        // gemm ids 0..390: bx<512 minus preceding hist blocks, else bx-128
        int gid = (bx < 512) ? (bx - ((bx + 1) >> 2)) : (bx - HIST_BLOCKS);
        gemm_fused_body<256>(gid, x, Wl1, Wr1, g_zl, g_zr);
    }
}

// ---------------- CSR scan: A (per-block partials) + BC (offsets applied) ----------------
__global__ void scanA_kernel() {
    __shared__ int sh[256];
    const int t = threadIdx.x;
    const int i = blockIdx.x * 256 + t;
    int v = (i < NN) ? g_deg[i] : 0;
    sh[t] = v;
    __syncthreads();
#pragma unroll
    for (int off = 1; off < 256; off <<= 1) {
        int u = (t >= off) ? sh[t - off] : 0;
        __syncthreads();
        sh[t] += u;
        __syncthreads();
    }
    if (i < NN) g_rowstart[i] = sh[t] - v;        // exclusive local prefix
    if (t == 255) g_bsum[blockIdx.x] = sh[255];   // block total
}

// Every block redundantly scans the NB block sums (NB=196 <= 256), then applies
// its own offset. Replaces the separate grid=1 scanB + scanC launches.
__global__ void scanBC_kernel() {
    __shared__ int sh[256];
    __shared__ int ex[256];
    const int t = threadIdx.x;
    int v = (t < NB) ? g_bsum[t] : 0;
    sh[t] = v;
    __syncthreads();
#pragma unroll
    for (int off = 1; off < 256; off <<= 1) {
        int u = (t >= off) ? sh[t - off] : 0;
        __syncthreads();
        sh[t] += u;
        __syncthreads();
    }
    ex[t] = sh[t] - v;                            // exclusive
    __syncthreads();
    const int boff = ex[blockIdx.x];
    const int i = blockIdx.x * 256 + t;
    if (i < NN) {
        int r = g_rowstart[i] + boff;
        g_rowstart[i] = r;
        g_cursor[i]   = r;
    }
    if (i == 0) g_rowstart[NN] = sh[NB - 1];      // grand total
}

__global__ void fill_kernel(const void* __restrict__ ei) {
    __shared__ int s_nz;
    bool is64 = detect_is64<256, 4>((const int*)ei, &s_nz);
    int e = blockIdx.x * blockDim.x + threadIdx.x;
    if (e < EE) {
        int d = edge_at(ei, is64, (long long)EE + e);
        int s = edge_at(ei, is64, e);
        if ((unsigned)d < NN && (unsigned)s < NN) {
            int pos = atomicAdd(&g_cursor[d], 1);
            g_esrc[pos] = s;
        }
    }
}

// ---------------- layer-2 fused GEMM ----------------
__global__ __launch_bounds__(512) void gemm_f2_kernel(const float* __restrict__ Wl2,
                                                      const float* __restrict__ Wr2) {
    gemm_fused_body<128>(blockIdx.x, g_h, Wl2, Wr2, g_ul, g_ur);
}

// ---------------- fused mean-aggregate + epilogue ----------------
// layer 1: h = relu(mean_agg(zl) + zr + b1), D=128, one warp per node, float4/lane
__global__ void agg_epi1_kernel(const float* __restrict__ b1) {
    int gw = (blockIdx.x * blockDim.x + threadIdx.x) >> 5;
    if (gw >= NN) return;
    int lane = threadIdx.x & 31;
    int c = lane * 4;
    int lo = g_rowstart[gw], hi = g_rowstart[gw + 1];

    float4 acc = make_float4(0.f, 0.f, 0.f, 0.f);
    int j = lo;
    for (; j + 4 <= hi; j += 4) {
        int s0 = g_esrc[j], s1 = g_esrc[j + 1], s2 = g_esrc[j + 2], s3 = g_esrc[j + 3];
        float4 v0 = *(const float4*)&g_zl[s0 * DHID + c];
        float4 v1 = *(const float4*)&g_zl[s1 * DHID + c];
        float4 v2 = *(const float4*)&g_zl[s2 * DHID + c];
        float4 v3 = *(const float4*)&g_zl[s3 * DHID + c];
        acc.x += (v0.x + v1.x) + (v2.x + v3.x);
        acc.y += (v0.y + v1.y) + (v2.y + v3.y);
        acc.z += (v0.z + v1.z) + (v2.z + v3.z);
        acc.w += (v0.w + v1.w) + (v2.w + v3.w);
    }
    for (; j < hi; j++) {
        int s = g_esrc[j];
        float4 v = *(const float4*)&g_zl[s * DHID + c];
        acc.x += v.x; acc.y += v.y; acc.z += v.z; acc.w += v.w;
    }
    float invd = 1.0f / (float)max(hi - lo, 1);
    float4 r  = *(const float4*)&g_zr[gw * DHID + c];
    float4 bb = *(const float4*)&b1[c];
    float4 o;
    o.x = fmaxf(fmaf(acc.x, invd, r.x + bb.x), 0.f);
    o.y = fmaxf(fmaf(acc.y, invd, r.y + bb.y), 0.f);
    o.z = fmaxf(fmaf(acc.z, invd, r.z + bb.z), 0.f);
    o.w = fmaxf(fmaf(acc.w, invd, r.w + bb.w), 0.f);
    *(float4*)&g_h[gw * DHID + c] = o;
}

// layer 2: out = mean_agg(ul) + ur + b2, D=64, one warp per node, float2/lane.
// Tail: zero g_deg for the NEXT launch (its last reader, scanA, already ran).
__global__ void agg_epi2_kernel(const float* __restrict__ b2, float* __restrict__ out) {
    int gw = (blockIdx.x * blockDim.x + threadIdx.x) >> 5;
    if (gw >= NN) return;
    int lane = threadIdx.x & 31;
    int c = lane * 2;
    int lo = g_rowstart[gw], hi = g_rowstart[gw + 1];

    float2 acc = make_float2(0.f, 0.f);
    int j = lo;
    for (; j + 4 <= hi; j += 4) {
        int s0 = g_esrc[j], s1 = g_esrc[j + 1], s2 = g_esrc[j + 2], s3 = g_esrc[j + 3];
        float2 v0 = *(const float2*)&g_ul[s0 * DOUT + c];
        float2 v1 = *(const float2*)&g_ul[s1 * DOUT + c];
        float2 v2 = *(const float2*)&g_ul[s2 * DOUT + c];
        float2 v3 = *(const float2*)&g_ul[s3 * DOUT + c];
        acc.x += (v0.x + v1.x) + (v2.x + v3.x);
        acc.y += (v0.y + v1.y) + (v2.y + v3.y);
    }
    for (; j < hi; j++) {
        int s = g_esrc[j];
        float2 v = *(const float2*)&g_ul[s * DOUT + c];
        acc.x += v.x; acc.y += v.y;
    }
    float invd = 1.0f / (float)max(hi - lo, 1);
    float2 r  = *(const float2*)&g_ur[gw * DOUT + c];
    float2 bb = *(const float2*)&b2[c];
    float2 o;
    o.x = fmaf(acc.x, invd, r.x + bb.x);
    o.y = fmaf(acc.y, invd, r.y + bb.y);
    *(float2*)&out[gw * DOUT + c] = o;

    if (lane == 0) g_deg[gw] = 0;   // reset for next launch
}

// ---------------- launch (single stream, 7 kernels) ----------------
extern "C" void kernel_launch(void* const* d_in, const int* in_sizes, int n_in,
                              void* d_out, int out_size) {
    const float* x   = (const float*)d_in[0];
    const void*  ei  = d_in[1];                 // int32 OR int64 — detected per-block
    const float* Wl1 = (const float*)d_in[2];
    const float* Wr1 = (const float*)d_in[3];
    const float* b1  = (const float*)d_in[4];
    const float* Wl2 = (const float*)d_in[5];
    const float* Wr2 = (const float*)d_in[6];
    const float* b2  = (const float*)d_in[7];
    float* out = (float*)d_out;

    // Opt-in to >48KB dynamic smem (host-side attribute, capture-legal, idempotent).
    cudaFuncSetAttribute(gemm1_hist_kernel, cudaFuncAttributeMaxDynamicSharedMemorySize, SMEM_F1);
    cudaFuncSetAttribute(gemm_f2_kernel,   cudaFuncAttributeMaxDynamicSharedMemorySize, SMEM_F2);

    // K1: layer-1 fused GEMM with histogram blocks interleaved (overlap, no streams)
    gemm1_hist_kernel<<<K1_GRID, 512, SMEM_F1>>>(x, Wl1, Wr1, ei);

    // CSR finish
    scanA_kernel<<<NB, 256>>>();
    scanBC_kernel<<<NB, 256>>>();
    fill_kernel<<<(EE + 255) / 256, 256>>>(ei);

    // layer-1 aggregate + epilogue
    agg_epi1_kernel<<<(NN * 32 + 255) / 256, 256>>>(b1);

    // layer-2 fused projections + aggregation
    gemm_f2_kernel<<<GEMM_GRID, 512, SMEM_F2>>>(Wl2, Wr2);
    agg_epi2_kernel<<<(NN * 32 + 255) / 256, 256>>>(b2, out);
}